// round 2
// baseline (speedup 1.0000x reference)
#include <cuda_runtime.h>

#define BATCH 512
#define IDIM 256
#define ODIM 256
#define CDIM 128
#define HDIM 128
#define IO (IDIM * ODIM)        // 65536
#define W2COLS (IO + ODIM)      // 65792

// scratch (allocation-free rule: __device__ globals)
__device__ float g_hT[HDIM * BATCH];   // [h][b], transposed
__device__ float g_xT[IDIM * BATCH];   // [i][b], transposed

// ---------------------------------------------------------------------------
// Kernel 1: hT[j][b] = relu(b1[j] + cond[b,:] @ w1[:,j])
// ---------------------------------------------------------------------------
__global__ void prep_h_kernel(const float* __restrict__ cond,
                              const float* __restrict__ w1,
                              const float* __restrict__ b1) {
    int idx = blockIdx.x * blockDim.x + threadIdx.x;  // 0..65535
    int b = idx >> 7;
    int j = idx & 127;
    float acc = b1[j];
    const float* c = cond + b * CDIM;
#pragma unroll 8
    for (int k = 0; k < CDIM; k++)
        acc = fmaf(c[k], w1[k * HDIM + j], acc);
    g_hT[j * BATCH + b] = fmaxf(acc, 0.0f);
}

// ---------------------------------------------------------------------------
// Kernel 2: xT[i][b] = x[b][i]
// ---------------------------------------------------------------------------
__global__ void prep_xT_kernel(const float* __restrict__ x) {
    int idx = blockIdx.x * blockDim.x + threadIdx.x;  // 0..131071
    int b = idx >> 8;
    int i = idx & 255;
    g_xT[i * BATCH + b] = x[idx];
}

// ---------------------------------------------------------------------------
// Kernel 3 (base/epilogue, PLAIN STORES — runs before the atomic GEMM):
// out[b,o] = base_bias[o] + b2[IO+o]
//          + sum_i x[b,i] * (baseW[i,o] + b2[i*256+o])
//          + sum_h h[b,h] * w2[h, IO+o]
// ---------------------------------------------------------------------------
__global__ void base_kernel(const float* __restrict__ x,
                            const float* __restrict__ baseW,
                            const float* __restrict__ base_bias,
                            const float* __restrict__ w2,
                            const float* __restrict__ b2,
                            float* __restrict__ out) {
    __shared__ float xs[16][IDIM];
    __shared__ float hs[HDIM][16];
    int b0 = blockIdx.x * 16;
    int o = threadIdx.x;  // 256 threads, one per output column

    for (int r = 0; r < 16; r++) {
        int e = r * 256 + o;
        xs[e >> 8][e & 255] = x[b0 * IDIM + e];
    }
    for (int r = 0; r < 8; r++) {
        int e = r * 256 + o;
        hs[e >> 4][e & 15] = g_hT[(e >> 4) * BATCH + b0 + (e & 15)];
    }
    __syncthreads();

    float acc[16];
    float bias = base_bias[o] + b2[IO + o];
#pragma unroll
    for (int b = 0; b < 16; b++) acc[b] = bias;

    for (int i = 0; i < IDIM; i++) {
        float w = baseW[i * ODIM + o] + b2[i * ODIM + o];
#pragma unroll
        for (int b = 0; b < 16; b++) acc[b] = fmaf(xs[b][i], w, acc[b]);
    }
    for (int hh = 0; hh < HDIM; hh++) {
        float w = w2[(size_t)hh * W2COLS + IO + o];
#pragma unroll
        for (int b = 0; b < 16; b++) acc[b] = fmaf(hs[hh][b], w, acc[b]);
    }
#pragma unroll
    for (int b = 0; b < 16; b++) out[(b0 + b) * ODIM + o] = acc[b];
}

// ---------------------------------------------------------------------------
// Kernel 4: the big GEMM with on-the-fly A.
//   out[b,o] += sum_k Z[b,k] * W2'[k,o],  k=(hh,i), K=32768
//   Z[b,k] = hT[hh][b] * xT[i][b]
//   W2'[k,o] = w2[hh*65792 + i*256 + o]
// Tiles: BM=128, BN=64, BK=32. 256 threads, 8x4 micro-tile, packed f32x2 FMA.
// Split-K=16 -> 256 blocks, atomicAdd reduction.
// ---------------------------------------------------------------------------
#define BM 128
#define BN 64
#define BK 32
#define SPLITK 16
#define KTOT (HDIM * IDIM)        // 32768
#define KCHUNK (KTOT / SPLITK)    // 2048

__global__ void __launch_bounds__(256, 2)
gemm_kernel(const float* __restrict__ w2, float* __restrict__ out) {
    __shared__ float As[BK][BM];  // [k][m] transposed for vector LDS along m
    __shared__ float Bs[BK][BN];

    int n0 = blockIdx.x * BN;
    int b0 = blockIdx.y * BM;
    int k0 = blockIdx.z * KCHUNK;
    int tid = threadIdx.x;
    int tn = (tid & 15) * 4;   // 16 n-groups of 4
    int tm = (tid >> 4) * 8;   // 16 m-groups of 8

    // fp32x2 accumulators: acc[j][n] holds rows (tm+2j, tm+2j+1), col tn+n
    unsigned long long acc[4][4];
#pragma unroll
    for (int j = 0; j < 4; j++)
#pragma unroll
        for (int n = 0; n < 4; n++) acc[j][n] = 0ull;

    for (int kt = 0; kt < KCHUNK; kt += BK) {
        int k = k0 + kt;
        int hh = k >> 8;       // constant within the BK tile (32 | 256)
        int i0 = k & 255;

        // A tile: As[t][m] = hT[hh][b0+m] * xT[i0+t][b0+m]  (coalesced, no conflicts)
        const float* hrow = g_hT + hh * BATCH + b0;
#pragma unroll
        for (int r = 0; r < 16; r++) {
            int e = r * 256 + tid;
            int t = e >> 7;
            int m = e & 127;
            As[t][m] = hrow[m] * g_xT[(i0 + t) * BATCH + b0 + m];
        }
        // B tile: Bs[t][n] = w2[hh][ (i0+t)*256 + n0+n ]
        const float* wb = w2 + (size_t)hh * W2COLS + (size_t)i0 * ODIM + n0;
#pragma unroll
        for (int r = 0; r < 8; r++) {
            int e = r * 256 + tid;
            int t = e >> 6;
            int n = e & 63;
            Bs[t][n] = wb[t * ODIM + n];
        }
        __syncthreads();

#pragma unroll
        for (int t = 0; t < BK; t++) {
            unsigned long long a2[4];
#pragma unroll
            for (int j = 0; j < 4; j++)
                a2[j] = *(const unsigned long long*)&As[t][tm + 2 * j];
            float4 bv = *(const float4*)&Bs[t][tn];
            unsigned long long bb[4];
            asm("mov.b64 %0,{%1,%1};" : "=l"(bb[0]) : "f"(bv.x));
            asm("mov.b64 %0,{%1,%1};" : "=l"(bb[1]) : "f"(bv.y));
            asm("mov.b64 %0,{%1,%1};" : "=l"(bb[2]) : "f"(bv.z));
            asm("mov.b64 %0,{%1,%1};" : "=l"(bb[3]) : "f"(bv.w));
#pragma unroll
            for (int j = 0; j < 4; j++)
#pragma unroll
                for (int n = 0; n < 4; n++)
                    asm("fma.rn.f32x2 %0,%1,%2,%0;"
                        : "+l"(acc[j][n]) : "l"(a2[j]), "l"(bb[n]));
        }
        __syncthreads();
    }

    // split-K reduction via atomics (base_kernel already wrote the base value)
#pragma unroll
    for (int j = 0; j < 4; j++) {
#pragma unroll
        for (int n = 0; n < 4; n++) {
            float lo, hi;
            asm("mov.b64 {%0,%1},%2;" : "=f"(lo), "=f"(hi) : "l"(acc[j][n]));
            int o = n0 + tn + n;
            atomicAdd(&out[(b0 + tm + 2 * j) * ODIM + o], lo);
            atomicAdd(&out[(b0 + tm + 2 * j + 1) * ODIM + o], hi);
        }
    }
}

// ---------------------------------------------------------------------------
extern "C" void kernel_launch(void* const* d_in, const int* in_sizes, int n_in,
                              void* d_out, int out_size) {
    const float* x    = (const float*)d_in[0];
    const float* cond = (const float*)d_in[1];
    const float* bw   = (const float*)d_in[2];
    const float* bb   = (const float*)d_in[3];
    const float* w1   = (const float*)d_in[4];
    const float* b1   = (const float*)d_in[5];
    const float* w2   = (const float*)d_in[6];
    const float* b2   = (const float*)d_in[7];
    float* out = (float*)d_out;

    prep_h_kernel<<<256, 256>>>(cond, w1, b1);
    prep_xT_kernel<<<512, 256>>>(x);
    base_kernel<<<32, 256>>>(x, bw, bb, w2, b2, out);
    gemm_kernel<<<dim3(ODIM / BN, BATCH / BM, SPLITK), 256>>>(w2, out);
}

// round 4
// speedup vs baseline: 1.3626x; 1.3626x over previous
#include <cuda_runtime.h>
#include <cuda_bf16.h>
#include <cstdint>

#define BATCH 512
#define IDIM 256
#define ODIM 256
#define CDIM 128
#define HDIM 128
#define IO (IDIM * ODIM)        // 65536
#define W2COLS (IO + ODIM)      // 65792
#define KTOT (HDIM * IDIM)      // 32768
#define SPLITK 32
#define KCHUNK (KTOT / SPLITK)  // 1024
#define BM 128
#define BN 128
#define BK 32
#define NSTAGES (KCHUNK / BK)   // 32

// ------------------------- device scratch (no allocs) -----------------------
__device__ float g_hT[HDIM * BATCH];                        // [h][b]
__device__ __nv_bfloat16 g_Zhi[(size_t)BATCH * KTOT];       // 32 MB, [b][k]
__device__ __nv_bfloat16 g_Zlo[(size_t)BATCH * KTOT];       // 32 MB
__device__ __nv_bfloat16 g_Whi[(size_t)ODIM * KTOT];        // 16 MB, [o][k]
__device__ __nv_bfloat16 g_Wlo[(size_t)ODIM * KTOT];        // 16 MB
__device__ float g_part[(size_t)SPLITK * BATCH * ODIM];     // 16 MB

// ------------------------- PTX helpers --------------------------------------
__device__ __forceinline__ uint32_t smem_u32(const void* p) {
    uint32_t a;
    asm("{ .reg .u64 t; cvta.to.shared.u64 t, %1; cvt.u32.u64 %0, t; }"
        : "=r"(a) : "l"(p));
    return a;
}
__device__ __forceinline__ void cp16(uint32_t s, const void* g) {
    asm volatile("cp.async.cg.shared.global [%0], [%1], 16;" :: "r"(s), "l"(g));
}
#define CP_COMMIT() asm volatile("cp.async.commit_group;" ::: "memory")
#define CP_WAIT(n)  asm volatile("cp.async.wait_group %0;" :: "n"(n) : "memory")

#define LDSM4(r0, r1, r2, r3, addr) \
    asm volatile("ldmatrix.sync.aligned.m8n8.x4.shared.b16 {%0,%1,%2,%3}, [%4];" \
        : "=r"(r0), "=r"(r1), "=r"(r2), "=r"(r3) : "r"(addr))

#define MMA16816(c, a, b0, b1) \
    asm volatile("mma.sync.aligned.m16n8k16.row.col.f32.bf16.bf16.f32 " \
        "{%0,%1,%2,%3}, {%4,%5,%6,%7}, {%8,%9}, {%0,%1,%2,%3};" \
        : "+f"((c)[0]), "+f"((c)[1]), "+f"((c)[2]), "+f"((c)[3]) \
        : "r"((a)[0]), "r"((a)[1]), "r"((a)[2]), "r"((a)[3]), "r"(b0), "r"(b1))

// ------------------------- prep kernels -------------------------------------
__global__ void prep_h_kernel(const float* __restrict__ cond,
                              const float* __restrict__ w1,
                              const float* __restrict__ b1) {
    int idx = blockIdx.x * blockDim.x + threadIdx.x;
    int b = idx >> 7, j = idx & 127;
    float acc = b1[j];
    const float* c = cond + b * CDIM;
#pragma unroll 8
    for (int k = 0; k < CDIM; k++) acc = fmaf(c[k], w1[k * HDIM + j], acc);
    g_hT[j * BATCH + b] = fmaxf(acc, 0.0f);
}

// Z[b][k] = h[b][k>>8] * x[b][k&255], split hi/lo bf16. 8 k per thread.
__global__ void prep_Z_kernel(const float* __restrict__ x) {
    int c = blockIdx.x * blockDim.x + threadIdx.x;   // 0..2097151
    int b = c >> 12;
    int rem = c & 4095;
    int hh = rem >> 5;
    int i0 = (rem & 31) * 8;
    float h = g_hT[hh * BATCH + b];
    float4 x0 = *(const float4*)(x + b * IDIM + i0);
    float4 x1 = *(const float4*)(x + b * IDIM + i0 + 4);
    float z[8] = {h*x0.x, h*x0.y, h*x0.z, h*x0.w, h*x1.x, h*x1.y, h*x1.z, h*x1.w};
    union { __nv_bfloat16 e[8]; uint4 v; } hi, lo;
#pragma unroll
    for (int j = 0; j < 8; j++) {
        hi.e[j] = __float2bfloat16(z[j]);
        lo.e[j] = __float2bfloat16(z[j] - __bfloat162float(hi.e[j]));
    }
    size_t g = ((size_t)b * KTOT + (size_t)hh * 256 + i0) / 8;
    ((uint4*)g_Zhi)[g] = hi.v;
    ((uint4*)g_Zlo)[g] = lo.v;
}

// W'[o][k] = w2[(k>>8)*W2COLS + (k&255)*256 + o], transposed + hi/lo split.
__global__ void prep_W_kernel(const float* __restrict__ w2) {
    __shared__ float ts[32][33];
    int kt = blockIdx.x * 32, ot = blockIdx.y * 32;
    int tx = threadIdx.x & 31, ty = threadIdx.x >> 5;   // ty: 0..7
#pragma unroll
    for (int r = 0; r < 4; r++) {
        int k = kt + ty + 8 * r;
        ts[ty + 8 * r][tx] = w2[(size_t)256 * (k + (k >> 8)) + ot + tx];
    }
    __syncthreads();
#pragma unroll
    for (int r = 0; r < 4; r++) {
        int o = ot + ty + 8 * r;
        float v = ts[tx][ty + 8 * r];
        __nv_bfloat16 hi = __float2bfloat16(v);
        __nv_bfloat16 lo = __float2bfloat16(v - __bfloat162float(hi));
        g_Whi[(size_t)o * KTOT + kt + tx] = hi;
        g_Wlo[(size_t)o * KTOT + kt + tx] = lo;
    }
}

// base part: out = bias + x@(baseW + reshape(b2)) + h@w2[:, IO:]
__global__ void base_kernel(const float* __restrict__ x,
                            const float* __restrict__ baseW,
                            const float* __restrict__ base_bias,
                            const float* __restrict__ w2,
                            const float* __restrict__ b2,
                            float* __restrict__ out) {
    __shared__ float xs[16][IDIM];
    __shared__ float hs[HDIM][16];
    int b0 = blockIdx.x * 16;
    int o = threadIdx.x;
    for (int r = 0; r < 16; r++) {
        int e = r * 256 + o;
        xs[e >> 8][e & 255] = x[b0 * IDIM + e];
    }
    for (int r = 0; r < 8; r++) {
        int e = r * 256 + o;
        hs[e >> 4][e & 15] = g_hT[(e >> 4) * BATCH + b0 + (e & 15)];
    }
    __syncthreads();
    float acc[16];
    float bias = base_bias[o] + b2[IO + o];
#pragma unroll
    for (int b = 0; b < 16; b++) acc[b] = bias;
    for (int i = 0; i < IDIM; i++) {
        float w = baseW[i * ODIM + o] + b2[i * ODIM + o];
#pragma unroll
        for (int b = 0; b < 16; b++) acc[b] = fmaf(xs[b][i], w, acc[b]);
    }
    for (int hh = 0; hh < HDIM; hh++) {
        float w = w2[(size_t)hh * W2COLS + IO + o];
#pragma unroll
        for (int b = 0; b < 16; b++) acc[b] = fmaf(hs[hh][b], w, acc[b]);
    }
#pragma unroll
    for (int b = 0; b < 16; b++) out[(b0 + b) * ODIM + o] = acc[b];
}

// ------------------------- HMMA GEMM (mma.sync bf16) ------------------------
// C[512,256] += Zhi@Whi^T + Zhi@Wlo^T + Zlo@Whi^T, K split 32 ways.
// CTA 128x128, BK=32, double-buffered cp.async, 8 warps (4m x 2n), warp 32x64.
// smem stage: Ahi(8K) Alo(8K) Bhi(8K) Blo(8K) = 32KB; 2 stages = 64KB.
#define STG_BYTES 32768
#define OFF_AHI 0
#define OFF_ALO 8192
#define OFF_BHI 16384
#define OFF_BLO 24576

__global__ void __launch_bounds__(256, 2)
gemm_hmma_kernel() {
    extern __shared__ char smem[];
    const uint32_t sbase = smem_u32(smem);
    const int tid = threadIdx.x;
    const int wid = tid >> 5, lane = tid & 31;
    const int n0 = blockIdx.x * BN;
    const int m0 = blockIdx.y * BM;
    const int ks = blockIdx.z * KCHUNK;

    const int m_base = (wid >> 1) * 32;   // 4 warps along M
    const int n_base = (wid & 1) * 64;    // 2 warps along N

    // ---- load lambda: stage kt into buffer kt&1 -----------------------------
    auto load_stage = [&](int kt) {
        uint32_t sb = sbase + (uint32_t)(kt & 1) * STG_BYTES;
        int kb = ks + kt * BK;
#pragma unroll
        for (int h = 0; h < 2; h++) {
            int t = tid + h * 256;
            int row = t >> 2, ch = t & 3;
            uint32_t sw = (uint32_t)row * 64 + ((ch ^ ((row >> 1) & 3)) << 4);
            size_t ga = (size_t)(m0 + row) * KTOT + kb + ch * 8;
            size_t gb = (size_t)(n0 + row) * KTOT + kb + ch * 8;
            cp16(sb + OFF_AHI + sw, g_Zhi + ga);
            cp16(sb + OFF_ALO + sw, g_Zlo + ga);
            cp16(sb + OFF_BHI + sw, g_Whi + gb);
            cp16(sb + OFF_BLO + sw, g_Wlo + gb);
        }
        CP_COMMIT();
    };

    float acc[2][8][4];
#pragma unroll
    for (int i = 0; i < 2; i++)
#pragma unroll
        for (int j = 0; j < 8; j++)
#pragma unroll
            for (int q = 0; q < 4; q++) acc[i][j][q] = 0.0f;

    // fragment smem address components (row parts are loop-invariant)
    const int arow_base = m_base + (lane & 15);          // + mf*16
    const int asel = lane >> 4;
    const int brow_base = n_base + ((lane >> 4) << 3) + (lane & 7);  // + np*16
    const int bsel = (lane >> 3) & 1;

    load_stage(0);

    for (int kt = 0; kt < NSTAGES; kt++) {
        if (kt + 1 < NSTAGES) load_stage(kt + 1);
        if (kt + 1 < NSTAGES) { CP_WAIT(1); } else { CP_WAIT(0); }
        __syncthreads();

        uint32_t sb = sbase + (uint32_t)(kt & 1) * STG_BYTES;

#pragma unroll
        for (int kk = 0; kk < 2; kk++) {
            uint32_t a[2][4], bh[4][4], bl[4][4];
            // A-hi fragments
#pragma unroll
            for (int mf = 0; mf < 2; mf++) {
                int row = arow_base + mf * 16;
                int chl = 2 * kk + asel;
                uint32_t ad = sb + OFF_AHI + row * 64 +
                              ((chl ^ ((row >> 1) & 3)) << 4);
                LDSM4(a[mf][0], a[mf][1], a[mf][2], a[mf][3], ad);
            }
            // B-hi and B-lo fragments
#pragma unroll
            for (int np = 0; np < 4; np++) {
                int row = brow_base + np * 16;
                int chl = 2 * kk + bsel;
                uint32_t boff = row * 64 + ((chl ^ ((row >> 1) & 3)) << 4);
                LDSM4(bh[np][0], bh[np][1], bh[np][2], bh[np][3], sb + OFF_BHI + boff);
                LDSM4(bl[np][0], bl[np][1], bl[np][2], bl[np][3], sb + OFF_BLO + boff);
            }
            // hi * hi
#pragma unroll
            for (int mf = 0; mf < 2; mf++)
#pragma unroll
                for (int np = 0; np < 4; np++) {
                    MMA16816(acc[mf][2 * np], a[mf], bh[np][0], bh[np][1]);
                    MMA16816(acc[mf][2 * np + 1], a[mf], bh[np][2], bh[np][3]);
                }
            // hi * lo
#pragma unroll
            for (int mf = 0; mf < 2; mf++)
#pragma unroll
                for (int np = 0; np < 4; np++) {
                    MMA16816(acc[mf][2 * np], a[mf], bl[np][0], bl[np][1]);
                    MMA16816(acc[mf][2 * np + 1], a[mf], bl[np][2], bl[np][3]);
                }
            // lo * hi (reload A from Alo)
#pragma unroll
            for (int mf = 0; mf < 2; mf++) {
                int row = arow_base + mf * 16;
                int chl = 2 * kk + asel;
                uint32_t ad = sb + OFF_ALO + row * 64 +
                              ((chl ^ ((row >> 1) & 3)) << 4);
                LDSM4(a[mf][0], a[mf][1], a[mf][2], a[mf][3], ad);
            }
#pragma unroll
            for (int mf = 0; mf < 2; mf++)
#pragma unroll
                for (int np = 0; np < 4; np++) {
                    MMA16816(acc[mf][2 * np], a[mf], bh[np][0], bh[np][1]);
                    MMA16816(acc[mf][2 * np + 1], a[mf], bh[np][2], bh[np][3]);
                }
        }
        __syncthreads();
    }

    // ---- epilogue: write fp32 partials ------------------------------------
    float* dst = g_part + (size_t)blockIdx.z * (BATCH * ODIM);
#pragma unroll
    for (int mf = 0; mf < 2; mf++) {
#pragma unroll
        for (int nf = 0; nf < 8; nf++) {
            int m = m0 + m_base + mf * 16 + (lane >> 2);
            int o = n0 + n_base + nf * 8 + (lane & 3) * 2;
            float2 v0 = make_float2(acc[mf][nf][0], acc[mf][nf][1]);
            float2 v1 = make_float2(acc[mf][nf][2], acc[mf][nf][3]);
            *(float2*)(dst + (size_t)m * ODIM + o) = v0;
            *(float2*)(dst + (size_t)(m + 8) * ODIM + o) = v1;
        }
    }
}

// ------------------------- split-K reduction --------------------------------
__global__ void reduce_kernel(float* __restrict__ out) {
    int b = blockIdx.x, o = threadIdx.x;
    float acc = out[b * ODIM + o];
#pragma unroll
    for (int s = 0; s < SPLITK; s++)
        acc += g_part[((size_t)s * BATCH + b) * ODIM + o];
    out[b * ODIM + o] = acc;
}

// ------------------------- launcher -----------------------------------------
extern "C" void kernel_launch(void* const* d_in, const int* in_sizes, int n_in,
                              void* d_out, int out_size) {
    const float* x    = (const float*)d_in[0];
    const float* cond = (const float*)d_in[1];
    const float* bw   = (const float*)d_in[2];
    const float* bb   = (const float*)d_in[3];
    const float* w1   = (const float*)d_in[4];
    const float* b1   = (const float*)d_in[5];
    const float* w2   = (const float*)d_in[6];
    const float* b2   = (const float*)d_in[7];
    float* out = (float*)d_out;

    cudaFuncSetAttribute(gemm_hmma_kernel,
                         cudaFuncAttributeMaxDynamicSharedMemorySize, 2 * STG_BYTES);

    prep_h_kernel<<<256, 256>>>(cond, w1, b1);
    prep_Z_kernel<<<8192, 256>>>(x);
    prep_W_kernel<<<dim3(KTOT / 32, ODIM / 32), 256>>>(w2);
    base_kernel<<<32, 256>>>(x, bw, bb, w2, b2, out);
    gemm_hmma_kernel<<<dim3(ODIM / BN, BATCH / BM, SPLITK), 256, 2 * STG_BYTES>>>();
    reduce_kernel<<<BATCH, 256>>>(out);
}

// round 5
// speedup vs baseline: 1.9668x; 1.4434x over previous
#include <cuda_runtime.h>
#include <cuda_bf16.h>
#include <cstdint>

#define BATCH 512
#define IDIM 256
#define ODIM 256
#define CDIM 128
#define HDIM 128
#define IO (IDIM * ODIM)        // 65536
#define W2COLS (IO + ODIM)      // 65792
#define KTOT (HDIM * IDIM)      // 32768
#define KE 384                  // extended K: 256 (x/base) + 128 (h/biascols)
#define SPLITK 32
#define KCHUNK (KTOT / SPLITK)  // 1024
#define BM 128
#define BN 128
#define BK 32
#define NSTAGES (KCHUNK / BK)   // 32
#define NST_EXT (KE / BK)       // 12

// ------------------------- device scratch (no allocs) -----------------------
__device__ float g_hT[HDIM * BATCH];                        // [h][b]
__device__ float g_hB[BATCH * HDIM];                        // [b][h]
__device__ __nv_bfloat16 g_Zhi[(size_t)BATCH * KTOT];       // 32 MB, [b][k]
__device__ __nv_bfloat16 g_Zlo[(size_t)BATCH * KTOT];       // 32 MB
__device__ __nv_bfloat16 g_Whi[(size_t)ODIM * KTOT];        // 16 MB, [o][k]
__device__ __nv_bfloat16 g_Wlo[(size_t)ODIM * KTOT];        // 16 MB
__device__ __nv_bfloat16 g_Zext_hi[(size_t)BATCH * KE];
__device__ __nv_bfloat16 g_Zext_lo[(size_t)BATCH * KE];
__device__ __nv_bfloat16 g_Wext_hi[(size_t)ODIM * KE];
__device__ __nv_bfloat16 g_Wext_lo[(size_t)ODIM * KE];
__device__ float g_part[(size_t)(SPLITK + 1) * BATCH * ODIM];

// ------------------------- PTX helpers --------------------------------------
__device__ __forceinline__ uint32_t smem_u32(const void* p) {
    uint32_t a;
    asm("{ .reg .u64 t; cvta.to.shared.u64 t, %1; cvt.u32.u64 %0, t; }"
        : "=r"(a) : "l"(p));
    return a;
}
__device__ __forceinline__ void cp16(uint32_t s, const void* g) {
    asm volatile("cp.async.cg.shared.global [%0], [%1], 16;" :: "r"(s), "l"(g));
}
#define CP_COMMIT() asm volatile("cp.async.commit_group;" ::: "memory")
#define CP_WAIT(n)  asm volatile("cp.async.wait_group %0;" :: "n"(n) : "memory")

#define LDSM4(r0, r1, r2, r3, addr) \
    asm volatile("ldmatrix.sync.aligned.m8n8.x4.shared.b16 {%0,%1,%2,%3}, [%4];" \
        : "=r"(r0), "=r"(r1), "=r"(r2), "=r"(r3) : "r"(addr))

#define MMA16816(c, a, b0, b1) \
    asm volatile("mma.sync.aligned.m16n8k16.row.col.f32.bf16.bf16.f32 " \
        "{%0,%1,%2,%3}, {%4,%5,%6,%7}, {%8,%9}, {%0,%1,%2,%3};" \
        : "+f"((c)[0]), "+f"((c)[1]), "+f"((c)[2]), "+f"((c)[3]) \
        : "r"((a)[0]), "r"((a)[1]), "r"((a)[2]), "r"((a)[3]), "r"(b0), "r"(b1))

__device__ __forceinline__ void bf16_split(float v, __nv_bfloat16& hi, __nv_bfloat16& lo) {
    hi = __float2bfloat16(v);
    lo = __float2bfloat16(v - __bfloat162float(hi));
}

// ------------------------- prep kernels -------------------------------------
__global__ void prep_h_kernel(const float* __restrict__ cond,
                              const float* __restrict__ w1,
                              const float* __restrict__ b1) {
    int idx = blockIdx.x * blockDim.x + threadIdx.x;
    int b = idx >> 7, j = idx & 127;
    float acc = b1[j];
    const float* c = cond + b * CDIM;
#pragma unroll 8
    for (int k = 0; k < CDIM; k++) acc = fmaf(c[k], w1[k * HDIM + j], acc);
    float r = fmaxf(acc, 0.0f);
    g_hT[j * BATCH + b] = r;
    g_hB[b * HDIM + j] = r;
}

// Z[b][k] = h[b][k>>8] * x[b][k&255], split hi/lo bf16. 8 k per thread.
__global__ void prep_Z_kernel(const float* __restrict__ x) {
    int c = blockIdx.x * blockDim.x + threadIdx.x;   // 0..2097151
    int b = c >> 12;
    int rem = c & 4095;
    int hh = rem >> 5;
    int i0 = (rem & 31) * 8;
    float h = g_hT[hh * BATCH + b];
    float4 x0 = *(const float4*)(x + b * IDIM + i0);
    float4 x1 = *(const float4*)(x + b * IDIM + i0 + 4);
    float z[8] = {h*x0.x, h*x0.y, h*x0.z, h*x0.w, h*x1.x, h*x1.y, h*x1.z, h*x1.w};
    union { __nv_bfloat16 e[8]; uint4 v; } hi, lo;
#pragma unroll
    for (int j = 0; j < 8; j++) bf16_split(z[j], hi.e[j], lo.e[j]);
    size_t g = ((size_t)b * KTOT + (size_t)hh * 256 + i0) / 8;
    ((uint4*)g_Zhi)[g] = hi.v;
    ((uint4*)g_Zlo)[g] = lo.v;
}

// W'[o][k] = w2[(k>>8)*W2COLS + (k&255)*256 + o], transposed + hi/lo split.
__global__ void prep_W_kernel(const float* __restrict__ w2) {
    __shared__ float ts[32][33];
    int kt = blockIdx.x * 32, ot = blockIdx.y * 32;
    int tx = threadIdx.x & 31, ty = threadIdx.x >> 5;   // ty: 0..7
#pragma unroll
    for (int r = 0; r < 4; r++) {
        int k = kt + ty + 8 * r;
        ts[ty + 8 * r][tx] = w2[(size_t)256 * (k + (k >> 8)) + ot + tx];
    }
    __syncthreads();
#pragma unroll
    for (int r = 0; r < 4; r++) {
        int o = ot + ty + 8 * r;
        __nv_bfloat16 hi, lo;
        bf16_split(ts[tx][ty + 8 * r], hi, lo);
        g_Whi[(size_t)o * KTOT + kt + tx] = hi;
        g_Wlo[(size_t)o * KTOT + kt + tx] = lo;
    }
}

// Zext[b][k] = x[b][k] (k<256) | h[b][k-256]
__global__ void prep_Zext_kernel(const float* __restrict__ x) {
    int b = blockIdx.x, k = threadIdx.x;   // 384 threads
    float v = (k < 256) ? x[b * IDIM + k] : g_hB[b * HDIM + (k - 256)];
    __nv_bfloat16 hi, lo;
    bf16_split(v, hi, lo);
    g_Zext_hi[b * KE + k] = hi;
    g_Zext_lo[b * KE + k] = lo;
}

// Wext[o][k] = baseW[k][o]+b2[k*256+o] (k<256) | w2[(k-256)*W2COLS + IO + o]
__global__ void prep_Wext_kernel(const float* __restrict__ baseW,
                                 const float* __restrict__ b2,
                                 const float* __restrict__ w2) {
    __shared__ float ts[32][33];
    int kt = blockIdx.x * 32, ot = blockIdx.y * 32;
    int tx = threadIdx.x & 31, ty = threadIdx.x >> 5;
#pragma unroll
    for (int r = 0; r < 4; r++) {
        int k = kt + ty + 8 * r;
        float v;
        if (k < 256) v = baseW[k * ODIM + ot + tx] + b2[k * ODIM + ot + tx];
        else         v = w2[(size_t)(k - 256) * W2COLS + IO + ot + tx];
        ts[ty + 8 * r][tx] = v;
    }
    __syncthreads();
#pragma unroll
    for (int r = 0; r < 4; r++) {
        int o = ot + ty + 8 * r;
        __nv_bfloat16 hi, lo;
        bf16_split(ts[tx][ty + 8 * r], hi, lo);
        g_Wext_hi[(size_t)o * KE + kt + tx] = hi;
        g_Wext_lo[(size_t)o * KE + kt + tx] = lo;
    }
}

// ------------------------- HMMA GEMM (mma.sync bf16) ------------------------
// C = Zhi@Whi^T + Zhi@Wlo^T + Zlo@Whi^T over K=32768 (z<32) plus the K=384
// extension slice (z==32). CTA 128x128, BK=32, double-buffered cp.async,
// 8 warps (4m x 2n). 264 CTAs -> one wave at 2 CTA/SM.
#define STG_BYTES 32768
#define OFF_AHI 0
#define OFF_ALO 8192
#define OFF_BHI 16384
#define OFF_BLO 24576

__global__ void __launch_bounds__(256, 2)
gemm_hmma_kernel() {
    extern __shared__ char smem[];
    const uint32_t sbase = smem_u32(smem);
    const int tid = threadIdx.x;
    const int wid = tid >> 5, lane = tid & 31;
    const int n0 = blockIdx.x * BN;
    const int m0 = blockIdx.y * BM;

    const bool ext = (blockIdx.z == SPLITK);
    const int nst = ext ? NST_EXT : NSTAGES;
    const size_t kstr = ext ? KE : KTOT;
    const int ks = ext ? 0 : blockIdx.z * KCHUNK;
    const __nv_bfloat16* __restrict__ Ahi = ext ? g_Zext_hi : g_Zhi;
    const __nv_bfloat16* __restrict__ Alo = ext ? g_Zext_lo : g_Zlo;
    const __nv_bfloat16* __restrict__ Bhi = ext ? g_Wext_hi : g_Whi;
    const __nv_bfloat16* __restrict__ Blo = ext ? g_Wext_lo : g_Wlo;

    const int m_base = (wid >> 1) * 32;   // 4 warps along M
    const int n_base = (wid & 1) * 64;    // 2 warps along N

    auto load_stage = [&](int kt) {
        uint32_t sb = sbase + (uint32_t)(kt & 1) * STG_BYTES;
        int kb = ks + kt * BK;
#pragma unroll
        for (int h = 0; h < 2; h++) {
            int t = tid + h * 256;
            int row = t >> 2, ch = t & 3;
            uint32_t sw = (uint32_t)row * 64 + ((ch ^ ((row >> 1) & 3)) << 4);
            size_t ga = (size_t)(m0 + row) * kstr + kb + ch * 8;
            size_t gb = (size_t)(n0 + row) * kstr + kb + ch * 8;
            cp16(sb + OFF_AHI + sw, Ahi + ga);
            cp16(sb + OFF_ALO + sw, Alo + ga);
            cp16(sb + OFF_BHI + sw, Bhi + gb);
            cp16(sb + OFF_BLO + sw, Blo + gb);
        }
        CP_COMMIT();
    };

    float acc[2][8][4];
#pragma unroll
    for (int i = 0; i < 2; i++)
#pragma unroll
        for (int j = 0; j < 8; j++)
#pragma unroll
            for (int q = 0; q < 4; q++) acc[i][j][q] = 0.0f;

    const int arow_base = m_base + (lane & 15);
    const int asel = lane >> 4;
    const int brow_base = n_base + ((lane >> 4) << 3) + (lane & 7);
    const int bsel = (lane >> 3) & 1;

    load_stage(0);

    for (int kt = 0; kt < nst; kt++) {
        if (kt + 1 < nst) { load_stage(kt + 1); CP_WAIT(1); }
        else             { CP_WAIT(0); }
        __syncthreads();

        uint32_t sb = sbase + (uint32_t)(kt & 1) * STG_BYTES;

#pragma unroll
        for (int kk = 0; kk < 2; kk++) {
            uint32_t a[2][4], bh[4][4], bl[4][4];
#pragma unroll
            for (int mf = 0; mf < 2; mf++) {
                int row = arow_base + mf * 16;
                int chl = 2 * kk + asel;
                uint32_t ad = sb + OFF_AHI + row * 64 +
                              ((chl ^ ((row >> 1) & 3)) << 4);
                LDSM4(a[mf][0], a[mf][1], a[mf][2], a[mf][3], ad);
            }
#pragma unroll
            for (int np = 0; np < 4; np++) {
                int row = brow_base + np * 16;
                int chl = 2 * kk + bsel;
                uint32_t boff = row * 64 + ((chl ^ ((row >> 1) & 3)) << 4);
                LDSM4(bh[np][0], bh[np][1], bh[np][2], bh[np][3], sb + OFF_BHI + boff);
                LDSM4(bl[np][0], bl[np][1], bl[np][2], bl[np][3], sb + OFF_BLO + boff);
            }
#pragma unroll
            for (int mf = 0; mf < 2; mf++)
#pragma unroll
                for (int np = 0; np < 4; np++) {
                    MMA16816(acc[mf][2 * np], a[mf], bh[np][0], bh[np][1]);
                    MMA16816(acc[mf][2 * np + 1], a[mf], bh[np][2], bh[np][3]);
                }
#pragma unroll
            for (int mf = 0; mf < 2; mf++)
#pragma unroll
                for (int np = 0; np < 4; np++) {
                    MMA16816(acc[mf][2 * np], a[mf], bl[np][0], bl[np][1]);
                    MMA16816(acc[mf][2 * np + 1], a[mf], bl[np][2], bl[np][3]);
                }
#pragma unroll
            for (int mf = 0; mf < 2; mf++) {
                int row = arow_base + mf * 16;
                int chl = 2 * kk + asel;
                uint32_t ad = sb + OFF_ALO + row * 64 +
                              ((chl ^ ((row >> 1) & 3)) << 4);
                LDSM4(a[mf][0], a[mf][1], a[mf][2], a[mf][3], ad);
            }
#pragma unroll
            for (int mf = 0; mf < 2; mf++)
#pragma unroll
                for (int np = 0; np < 4; np++) {
                    MMA16816(acc[mf][2 * np], a[mf], bh[np][0], bh[np][1]);
                    MMA16816(acc[mf][2 * np + 1], a[mf], bh[np][2], bh[np][3]);
                }
        }
        __syncthreads();
    }

    float* dst = g_part + (size_t)blockIdx.z * (BATCH * ODIM);
#pragma unroll
    for (int mf = 0; mf < 2; mf++) {
#pragma unroll
        for (int nf = 0; nf < 8; nf++) {
            int m = m0 + m_base + mf * 16 + (lane >> 2);
            int o = n0 + n_base + nf * 8 + (lane & 3) * 2;
            float2 v0 = make_float2(acc[mf][nf][0], acc[mf][nf][1]);
            float2 v1 = make_float2(acc[mf][nf][2], acc[mf][nf][3]);
            *(float2*)(dst + (size_t)m * ODIM + o) = v0;
            *(float2*)(dst + (size_t)(m + 8) * ODIM + o) = v1;
        }
    }
}

// ------------------------- split-K reduction + bias --------------------------
__global__ void reduce_kernel(const float* __restrict__ base_bias,
                              const float* __restrict__ b2,
                              float* __restrict__ out) {
    int b = blockIdx.x, o = threadIdx.x;
    float acc = base_bias[o] + b2[IO + o];
#pragma unroll
    for (int s = 0; s <= SPLITK; s++)
        acc += g_part[((size_t)s * BATCH + b) * ODIM + o];
    out[b * ODIM + o] = acc;
}

// ------------------------- launcher -----------------------------------------
extern "C" void kernel_launch(void* const* d_in, const int* in_sizes, int n_in,
                              void* d_out, int out_size) {
    const float* x    = (const float*)d_in[0];
    const float* cond = (const float*)d_in[1];
    const float* bw   = (const float*)d_in[2];
    const float* bb   = (const float*)d_in[3];
    const float* w1   = (const float*)d_in[4];
    const float* b1   = (const float*)d_in[5];
    const float* w2   = (const float*)d_in[6];
    const float* b2   = (const float*)d_in[7];
    float* out = (float*)d_out;

    cudaFuncSetAttribute(gemm_hmma_kernel,
                         cudaFuncAttributeMaxDynamicSharedMemorySize, 2 * STG_BYTES);

    prep_h_kernel<<<256, 256>>>(cond, w1, b1);
    prep_Z_kernel<<<8192, 256>>>(x);
    prep_W_kernel<<<dim3(KTOT / 32, ODIM / 32), 256>>>(w2);
    prep_Zext_kernel<<<BATCH, KE>>>(x);
    prep_Wext_kernel<<<dim3(KE / 32, ODIM / 32), 256>>>(bw, b2, w2);
    gemm_hmma_kernel<<<dim3(ODIM / BN, BATCH / BM, SPLITK + 1), 256, 2 * STG_BYTES>>>();
    reduce_kernel<<<BATCH, 256>>>(bb, b2, out);
}

// round 6
// speedup vs baseline: 2.0176x; 1.0258x over previous
#include <cuda_runtime.h>
#include <cuda_bf16.h>
#include <cstdint>

#define BATCH 512
#define IDIM 256
#define ODIM 256
#define CDIM 128
#define HDIM 128
#define IO (IDIM * ODIM)        // 65536
#define W2COLS (IO + ODIM)      // 65792
#define KTOT (HDIM * IDIM)      // 32768
#define KE 384                  // extended K: 256 (x/base) + 128 (h/biascols)
#define NSLICE 36               // main K slices (uneven: 16x29 + 20x28 BK-units)
#define NSLICES_ALL (NSLICE + 1)
#define BM 256
#define BN 128
#define BK 32
#define NST_EXT (KE / BK)       // 12

// ------------------------- device scratch (no allocs) -----------------------
__device__ float g_hT[HDIM * BATCH];                        // [h][b]
__device__ float g_hB[BATCH * HDIM];                        // [b][h]
__device__ __nv_bfloat16 g_Zhi[(size_t)BATCH * KTOT];       // 32 MB, [b][k]
__device__ __nv_bfloat16 g_Zlo[(size_t)BATCH * KTOT];       // 32 MB
__device__ __nv_bfloat16 g_Whi[(size_t)ODIM * KTOT];        // 16 MB, [o][k]
__device__ __nv_bfloat16 g_Wlo[(size_t)ODIM * KTOT];        // 16 MB
__device__ __nv_bfloat16 g_Zext_hi[(size_t)BATCH * KE];
__device__ __nv_bfloat16 g_Zext_lo[(size_t)BATCH * KE];
__device__ __nv_bfloat16 g_Wext_hi[(size_t)ODIM * KE];
__device__ __nv_bfloat16 g_Wext_lo[(size_t)ODIM * KE];
__device__ float g_part[(size_t)NSLICES_ALL * BATCH * ODIM];

// ------------------------- PTX helpers --------------------------------------
__device__ __forceinline__ uint32_t smem_u32(const void* p) {
    uint32_t a;
    asm("{ .reg .u64 t; cvta.to.shared.u64 t, %1; cvt.u32.u64 %0, t; }"
        : "=r"(a) : "l"(p));
    return a;
}
__device__ __forceinline__ void cp16(uint32_t s, const void* g) {
    asm volatile("cp.async.cg.shared.global [%0], [%1], 16;" :: "r"(s), "l"(g));
}
#define CP_COMMIT() asm volatile("cp.async.commit_group;" ::: "memory")
#define CP_WAIT(n)  asm volatile("cp.async.wait_group %0;" :: "n"(n) : "memory")

#define LDSM4(r0, r1, r2, r3, addr) \
    asm volatile("ldmatrix.sync.aligned.m8n8.x4.shared.b16 {%0,%1,%2,%3}, [%4];" \
        : "=r"(r0), "=r"(r1), "=r"(r2), "=r"(r3) : "r"(addr))

#define MMA16816(c, a, b0, b1) \
    asm volatile("mma.sync.aligned.m16n8k16.row.col.f32.bf16.bf16.f32 " \
        "{%0,%1,%2,%3}, {%4,%5,%6,%7}, {%8,%9}, {%0,%1,%2,%3};" \
        : "+f"((c)[0]), "+f"((c)[1]), "+f"((c)[2]), "+f"((c)[3]) \
        : "r"((a)[0]), "r"((a)[1]), "r"((a)[2]), "r"((a)[3]), "r"(b0), "r"(b1))

__device__ __forceinline__ void bf16_split(float v, __nv_bfloat16& hi, __nv_bfloat16& lo) {
    hi = __float2bfloat16(v);
    lo = __float2bfloat16(v - __bfloat162float(hi));
}

// ------------------------- prep kernels -------------------------------------
__global__ void prep_h_kernel(const float* __restrict__ cond,
                              const float* __restrict__ w1,
                              const float* __restrict__ b1) {
    int idx = blockIdx.x * blockDim.x + threadIdx.x;
    int b = idx >> 7, j = idx & 127;
    float acc = b1[j];
    const float* c = cond + b * CDIM;
#pragma unroll 8
    for (int k = 0; k < CDIM; k++) acc = fmaf(c[k], w1[k * HDIM + j], acc);
    float r = fmaxf(acc, 0.0f);
    g_hT[j * BATCH + b] = r;
    g_hB[b * HDIM + j] = r;
}

// Z[b][k] = h[b][k>>8] * x[b][k&255] hi/lo split (blocks < 8192);
// blocks >= 8192 handle the Zext slice: [x | h] hi/lo split.
__global__ void prep_Z_kernel(const float* __restrict__ x) {
    if (blockIdx.x < 8192) {
        int c = blockIdx.x * blockDim.x + threadIdx.x;   // 0..2097151
        int b = c >> 12;
        int rem = c & 4095;
        int hh = rem >> 5;
        int i0 = (rem & 31) * 8;
        float h = g_hT[hh * BATCH + b];
        float4 x0 = *(const float4*)(x + b * IDIM + i0);
        float4 x1 = *(const float4*)(x + b * IDIM + i0 + 4);
        float z[8] = {h*x0.x, h*x0.y, h*x0.z, h*x0.w, h*x1.x, h*x1.y, h*x1.z, h*x1.w};
        union { __nv_bfloat16 e[8]; uint4 v; } hi, lo;
#pragma unroll
        for (int j = 0; j < 8; j++) bf16_split(z[j], hi.e[j], lo.e[j]);
        size_t g = ((size_t)b * KTOT + (size_t)hh * 256 + i0) / 8;
        ((uint4*)g_Zhi)[g] = hi.v;
        ((uint4*)g_Zlo)[g] = lo.v;
    } else {
        int idx = (blockIdx.x - 8192) * blockDim.x + threadIdx.x;  // 0..196607
        int b = idx / KE, k = idx - b * KE;
        float v = (k < 256) ? x[b * IDIM + k] : g_hB[b * HDIM + (k - 256)];
        __nv_bfloat16 hi, lo;
        bf16_split(v, hi, lo);
        g_Zext_hi[b * KE + k] = hi;
        g_Zext_lo[b * KE + k] = lo;
    }
}

// W'[o][k] transpose + hi/lo split; bx >= 1024 handles the Wext slice.
__global__ void prep_W_kernel(const float* __restrict__ w2,
                              const float* __restrict__ baseW,
                              const float* __restrict__ b2) {
    __shared__ float ts[32][33];
    bool ext = (blockIdx.x >= 1024);
    int kt = (ext ? (blockIdx.x - 1024) : blockIdx.x) * 32;
    int ot = blockIdx.y * 32;
    int tx = threadIdx.x & 31, ty = threadIdx.x >> 5;   // ty: 0..7
#pragma unroll
    for (int r = 0; r < 4; r++) {
        int k = kt + ty + 8 * r;
        float v;
        if (!ext) {
            v = w2[(size_t)256 * (k + (k >> 8)) + ot + tx];
        } else if (k < 256) {
            v = baseW[k * ODIM + ot + tx] + b2[k * ODIM + ot + tx];
        } else {
            v = w2[(size_t)(k - 256) * W2COLS + IO + ot + tx];
        }
        ts[ty + 8 * r][tx] = v;
    }
    __syncthreads();
#pragma unroll
    for (int r = 0; r < 4; r++) {
        int o = ot + ty + 8 * r;
        __nv_bfloat16 hi, lo;
        bf16_split(ts[tx][ty + 8 * r], hi, lo);
        if (!ext) {
            g_Whi[(size_t)o * KTOT + kt + tx] = hi;
            g_Wlo[(size_t)o * KTOT + kt + tx] = lo;
        } else {
            g_Wext_hi[(size_t)o * KE + kt + tx] = hi;
            g_Wext_lo[(size_t)o * KE + kt + tx] = lo;
        }
    }
}

// ------------------------- HMMA GEMM (mma.sync bf16) ------------------------
// BM=256 x BN=128 CTA, 512 threads (16 warps, 4m x 4n, warp 64x32), BK=32,
// 4-stage cp.async pipeline. grid 2x2x37 = 148 CTAs = one per SM.
// K split: 36 uneven main slices (16x29 + 20x28 BK-units) + 1 ext slice.
#define STG_BYTES 49152
#define OFF_AHI 0
#define OFF_ALO 16384
#define OFF_BHI 32768
#define OFF_BLO 40960
#define SMEM_TOTAL (4 * STG_BYTES)   // 192 KB

__global__ void __launch_bounds__(512, 1)
gemm_hmma_kernel() {
    extern __shared__ char smem[];
    const uint32_t sbase = smem_u32(smem);
    const int tid = threadIdx.x;
    const int wid = tid >> 5, lane = tid & 31;
    const int n0 = blockIdx.x * BN;
    const int m0 = blockIdx.y * BM;
    const int z = blockIdx.z;

    const bool ext = (z == NSLICE);
    const int nst = ext ? NST_EXT : (28 + (z < 16 ? 1 : 0));
    const int ks = ext ? 0 : (28 * z + min(z, 16)) * BK;
    const size_t kstr = ext ? KE : KTOT;
    const __nv_bfloat16* __restrict__ Ahi = ext ? g_Zext_hi : g_Zhi;
    const __nv_bfloat16* __restrict__ Alo = ext ? g_Zext_lo : g_Zlo;
    const __nv_bfloat16* __restrict__ Bhi = ext ? g_Wext_hi : g_Whi;
    const __nv_bfloat16* __restrict__ Blo = ext ? g_Wext_lo : g_Wlo;

    const int m_base = (wid >> 2) * 64;   // 4 warps along M
    const int n_base = (wid & 3) * 32;    // 4 warps along N

    auto load_stage = [&](int kt) {
        uint32_t sb = sbase + (uint32_t)(kt & 3) * STG_BYTES;
        int kb = ks + kt * BK;
        // A: 256 rows x 64B x {hi,lo} -> 2048 cp16, 4 per thread
#pragma unroll
        for (int h = 0; h < 2; h++) {
            int t = tid + h * 512;
            int row = t >> 2, ch = t & 3;
            uint32_t sw = (uint32_t)row * 64 + ((ch ^ ((row >> 1) & 3)) << 4);
            size_t ga = (size_t)(m0 + row) * kstr + kb + ch * 8;
            cp16(sb + OFF_AHI + sw, Ahi + ga);
            cp16(sb + OFF_ALO + sw, Alo + ga);
        }
        // B: 128 rows x 64B x {hi,lo} -> 1024 cp16, 2 per thread
        {
            int row = tid >> 2, ch = tid & 3;
            uint32_t sw = (uint32_t)row * 64 + ((ch ^ ((row >> 1) & 3)) << 4);
            size_t gb = (size_t)(n0 + row) * kstr + kb + ch * 8;
            cp16(sb + OFF_BHI + sw, Bhi + gb);
            cp16(sb + OFF_BLO + sw, Blo + gb);
        }
    };

    float acc[4][4][4];
#pragma unroll
    for (int i = 0; i < 4; i++)
#pragma unroll
        for (int j = 0; j < 4; j++)
#pragma unroll
            for (int q = 0; q < 4; q++) acc[i][j][q] = 0.0f;

    const int arow_base = m_base + (lane & 15);
    const int asel = lane >> 4;
    const int brow_base = n_base + ((lane >> 4) << 3) + (lane & 7);
    const int bsel = (lane >> 3) & 1;

    // prologue: stages 0..2
#pragma unroll
    for (int s = 0; s < 3; s++) { load_stage(s); CP_COMMIT(); }

    for (int kt = 0; kt < nst; kt++) {
        CP_WAIT(2);            // stage kt arrived
        __syncthreads();       // all warps done with stage kt-1 & see stage kt
        if (kt + 3 < nst) load_stage(kt + 3);
        CP_COMMIT();

        uint32_t sb = sbase + (uint32_t)(kt & 3) * STG_BYTES;

#pragma unroll
        for (int kk = 0; kk < 2; kk++) {
            uint32_t a[4][4], bh[2][4], bl[2][4];
#pragma unroll
            for (int mf = 0; mf < 4; mf++) {
                int row = arow_base + mf * 16;
                int chl = 2 * kk + asel;
                uint32_t ad = sb + OFF_AHI + row * 64 +
                              ((chl ^ ((row >> 1) & 3)) << 4);
                LDSM4(a[mf][0], a[mf][1], a[mf][2], a[mf][3], ad);
            }
#pragma unroll
            for (int np = 0; np < 2; np++) {
                int row = brow_base + np * 16;
                int chl = 2 * kk + bsel;
                uint32_t boff = row * 64 + ((chl ^ ((row >> 1) & 3)) << 4);
                LDSM4(bh[np][0], bh[np][1], bh[np][2], bh[np][3], sb + OFF_BHI + boff);
                LDSM4(bl[np][0], bl[np][1], bl[np][2], bl[np][3], sb + OFF_BLO + boff);
            }
            // hi*hi
#pragma unroll
            for (int mf = 0; mf < 4; mf++)
#pragma unroll
                for (int np = 0; np < 2; np++) {
                    MMA16816(acc[mf][2 * np], a[mf], bh[np][0], bh[np][1]);
                    MMA16816(acc[mf][2 * np + 1], a[mf], bh[np][2], bh[np][3]);
                }
            // hi*lo
#pragma unroll
            for (int mf = 0; mf < 4; mf++)
#pragma unroll
                for (int np = 0; np < 2; np++) {
                    MMA16816(acc[mf][2 * np], a[mf], bl[np][0], bl[np][1]);
                    MMA16816(acc[mf][2 * np + 1], a[mf], bl[np][2], bl[np][3]);
                }
            // lo*hi (reload A from Alo)
#pragma unroll
            for (int mf = 0; mf < 4; mf++) {
                int row = arow_base + mf * 16;
                int chl = 2 * kk + asel;
                uint32_t ad = sb + OFF_ALO + row * 64 +
                              ((chl ^ ((row >> 1) & 3)) << 4);
                LDSM4(a[mf][0], a[mf][1], a[mf][2], a[mf][3], ad);
            }
#pragma unroll
            for (int mf = 0; mf < 4; mf++)
#pragma unroll
                for (int np = 0; np < 2; np++) {
                    MMA16816(acc[mf][2 * np], a[mf], bh[np][0], bh[np][1]);
                    MMA16816(acc[mf][2 * np + 1], a[mf], bh[np][2], bh[np][3]);
                }
        }
    }
    CP_WAIT(0);

    float* dst = g_part + (size_t)z * (BATCH * ODIM);
#pragma unroll
    for (int mf = 0; mf < 4; mf++) {
#pragma unroll
        for (int nf = 0; nf < 4; nf++) {
            int m = m0 + m_base + mf * 16 + (lane >> 2);
            int o = n0 + n_base + nf * 8 + (lane & 3) * 2;
            float2 v0 = make_float2(acc[mf][nf][0], acc[mf][nf][1]);
            float2 v1 = make_float2(acc[mf][nf][2], acc[mf][nf][3]);
            *(float2*)(dst + (size_t)m * ODIM + o) = v0;
            *(float2*)(dst + (size_t)(m + 8) * ODIM + o) = v1;
        }
    }
}

// ------------------------- split-K reduction + bias --------------------------
__global__ void reduce_kernel(const float* __restrict__ base_bias,
                              const float* __restrict__ b2,
                              float* __restrict__ out) {
    int b = blockIdx.x, o = threadIdx.x;
    float acc = base_bias[o] + b2[IO + o];
#pragma unroll
    for (int s = 0; s < NSLICES_ALL; s++)
        acc += g_part[((size_t)s * BATCH + b) * ODIM + o];
    out[b * ODIM + o] = acc;
}

// ------------------------- launcher -----------------------------------------
extern "C" void kernel_launch(void* const* d_in, const int* in_sizes, int n_in,
                              void* d_out, int out_size) {
    const float* x    = (const float*)d_in[0];
    const float* cond = (const float*)d_in[1];
    const float* bw   = (const float*)d_in[2];
    const float* bb   = (const float*)d_in[3];
    const float* w1   = (const float*)d_in[4];
    const float* b1   = (const float*)d_in[5];
    const float* w2   = (const float*)d_in[6];
    const float* b2   = (const float*)d_in[7];
    float* out = (float*)d_out;

    cudaFuncSetAttribute(gemm_hmma_kernel,
                         cudaFuncAttributeMaxDynamicSharedMemorySize, SMEM_TOTAL);

    prep_h_kernel<<<256, 256>>>(cond, w1, b1);
    prep_Z_kernel<<<8192 + 768, 256>>>(x);
    prep_W_kernel<<<dim3(1024 + NST_EXT, ODIM / 32), 256>>>(w2, bw, b2);
    gemm_hmma_kernel<<<dim3(ODIM / BN, BATCH / BM, NSLICES_ALL), 512, SMEM_TOTAL>>>();
    reduce_kernel<<<BATCH, 256>>>(bb, b2, out);
}

// round 7
// speedup vs baseline: 2.4759x; 1.2272x over previous
#include <cuda_runtime.h>
#include <cuda_fp16.h>
#include <cstdint>

#define BATCH 512
#define IDIM 256
#define ODIM 256
#define CDIM 128
#define HDIM 128
#define IO (IDIM * ODIM)        // 65536
#define W2COLS (IO + ODIM)      // 65792
#define KTOT (HDIM * IDIM)      // 32768
#define KE 384                  // extended K: 256 (x/base) + 128 (h/biascols)
#define NSLICE 36               // main K slices over 512 BK-units: 8x15 + 28x14
#define NSLICES_ALL (NSLICE + 1)
#define BM 256
#define BN 128
#define BK 64
#define NST_EXT (KE / BK)       // 6

// ------------------------- device scratch (no allocs) -----------------------
__device__ float g_hT[HDIM * BATCH];                        // [h][b]
__device__ float g_hB[BATCH * HDIM];                        // [b][h]
__device__ __half g_Z[(size_t)BATCH * KTOT];                // 32 MB, [b][k]
__device__ __half g_Whi[(size_t)ODIM * KTOT];               // 16 MB, [o][k]
__device__ __half g_Wlo[(size_t)ODIM * KTOT];               // 16 MB
__device__ __half g_Zext[(size_t)BATCH * KE];
__device__ __half g_Wext_hi[(size_t)ODIM * KE];
__device__ __half g_Wext_lo[(size_t)ODIM * KE];
__device__ float g_part[(size_t)NSLICES_ALL * BATCH * ODIM];

// ------------------------- PTX helpers --------------------------------------
__device__ __forceinline__ uint32_t smem_u32(const void* p) {
    uint32_t a;
    asm("{ .reg .u64 t; cvta.to.shared.u64 t, %1; cvt.u32.u64 %0, t; }"
        : "=r"(a) : "l"(p));
    return a;
}
__device__ __forceinline__ void cp16(uint32_t s, const void* g) {
    asm volatile("cp.async.cg.shared.global [%0], [%1], 16;" :: "r"(s), "l"(g));
}
#define CP_COMMIT() asm volatile("cp.async.commit_group;" ::: "memory")
#define CP_WAIT(n)  asm volatile("cp.async.wait_group %0;" :: "n"(n) : "memory")

#define LDSM4(r0, r1, r2, r3, addr) \
    asm volatile("ldmatrix.sync.aligned.m8n8.x4.shared.b16 {%0,%1,%2,%3}, [%4];" \
        : "=r"(r0), "=r"(r1), "=r"(r2), "=r"(r3) : "r"(addr))

#define MMA16816(c, a, b0, b1) \
    asm volatile("mma.sync.aligned.m16n8k16.row.col.f32.f16.f16.f32 " \
        "{%0,%1,%2,%3}, {%4,%5,%6,%7}, {%8,%9}, {%0,%1,%2,%3};" \
        : "+f"((c)[0]), "+f"((c)[1]), "+f"((c)[2]), "+f"((c)[3]) \
        : "r"((a)[0]), "r"((a)[1]), "r"((a)[2]), "r"((a)[3]), "r"(b0), "r"(b1))

__device__ __forceinline__ void f16_split(float v, __half& hi, __half& lo) {
    hi = __float2half_rn(v);
    lo = __float2half_rn(v - __half2float(hi));
}

// ------------------------- prep kernels -------------------------------------
__global__ void prep_h_kernel(const float* __restrict__ cond,
                              const float* __restrict__ w1,
                              const float* __restrict__ b1) {
    int idx = blockIdx.x * blockDim.x + threadIdx.x;
    int b = idx >> 7, j = idx & 127;
    float acc = b1[j];
    const float* c = cond + b * CDIM;
#pragma unroll 8
    for (int k = 0; k < CDIM; k++) acc = fmaf(c[k], w1[k * HDIM + j], acc);
    float r = fmaxf(acc, 0.0f);
    g_hT[j * BATCH + b] = r;
    g_hB[b * HDIM + j] = r;
}

// Z[b][k] = fp16( h[b][k>>8] * x[b][k&255] ); blocks >= 8192 fill Zext = [x|h].
__global__ void prep_Z_kernel(const float* __restrict__ x) {
    if (blockIdx.x < 8192) {
        int c = blockIdx.x * blockDim.x + threadIdx.x;   // 0..2097151
        int b = c >> 12;
        int rem = c & 4095;
        int hh = rem >> 5;
        int i0 = (rem & 31) * 8;
        float h = g_hT[hh * BATCH + b];
        float4 x0 = *(const float4*)(x + b * IDIM + i0);
        float4 x1 = *(const float4*)(x + b * IDIM + i0 + 4);
        float z[8] = {h*x0.x, h*x0.y, h*x0.z, h*x0.w, h*x1.x, h*x1.y, h*x1.z, h*x1.w};
        union { __half e[8]; uint4 v; } o;
#pragma unroll
        for (int j = 0; j < 8; j++) o.e[j] = __float2half_rn(z[j]);
        size_t g = ((size_t)b * KTOT + (size_t)hh * 256 + i0) / 8;
        ((uint4*)g_Z)[g] = o.v;
    } else {
        int idx = (blockIdx.x - 8192) * blockDim.x + threadIdx.x;  // 0..196607
        int b = idx / KE, k = idx - b * KE;
        float v = (k < 256) ? x[b * IDIM + k] : g_hB[b * HDIM + (k - 256)];
        g_Zext[b * KE + k] = __float2half_rn(v);
    }
}

// W'[o][k] transpose + fp16 hi/lo split; bx >= 1024 handles the Wext slice.
__global__ void prep_W_kernel(const float* __restrict__ w2,
                              const float* __restrict__ baseW,
                              const float* __restrict__ b2) {
    __shared__ float ts[32][33];
    bool ext = (blockIdx.x >= 1024);
    int kt = (ext ? (blockIdx.x - 1024) : blockIdx.x) * 32;
    int ot = blockIdx.y * 32;
    int tx = threadIdx.x & 31, ty = threadIdx.x >> 5;   // ty: 0..7
#pragma unroll
    for (int r = 0; r < 4; r++) {
        int k = kt + ty + 8 * r;
        float v;
        if (!ext) {
            v = w2[(size_t)256 * (k + (k >> 8)) + ot + tx];
        } else if (k < 256) {
            v = baseW[k * ODIM + ot + tx] + b2[k * ODIM + ot + tx];
        } else {
            v = w2[(size_t)(k - 256) * W2COLS + IO + ot + tx];
        }
        ts[ty + 8 * r][tx] = v;
    }
    __syncthreads();
#pragma unroll
    for (int r = 0; r < 4; r++) {
        int o = ot + ty + 8 * r;
        __half hi, lo;
        f16_split(ts[tx][ty + 8 * r], hi, lo);
        if (!ext) {
            g_Whi[(size_t)o * KTOT + kt + tx] = hi;
            g_Wlo[(size_t)o * KTOT + kt + tx] = lo;
        } else {
            g_Wext_hi[(size_t)o * KE + kt + tx] = hi;
            g_Wext_lo[(size_t)o * KE + kt + tx] = lo;
        }
    }
}

// ------------------------- HMMA GEMM (mma.sync fp16, 2-term) ----------------
// C = Z@Whi^T + Z@Wlo^T. BM=256 x BN=128, 512 threads (16 warps, 4m x 4n),
// BK=64, 3-stage cp.async pipeline (192 KB). grid 2x2x37 = 148 CTAs.
// K split: 512 BK-units = 8 slices x15 + 28 slices x14, + 1 ext slice (6).
#define STG_BYTES 65536
#define OFF_A 0
#define OFF_BHI 32768
#define OFF_BLO 49152
#define SMEM_TOTAL (3 * STG_BYTES)   // 192 KB

__global__ void __launch_bounds__(512, 1)
gemm_hmma_kernel() {
    extern __shared__ char smem[];
    const uint32_t sbase = smem_u32(smem);
    const int tid = threadIdx.x;
    const int wid = tid >> 5, lane = tid & 31;
    const int n0 = blockIdx.x * BN;
    const int m0 = blockIdx.y * BM;
    const int z = blockIdx.z;

    const bool ext = (z == NSLICE);
    const int nst = ext ? NST_EXT : (14 + (z < 8 ? 1 : 0));
    const int ks = ext ? 0 : (14 * z + min(z, 8)) * BK;
    const size_t kstr = ext ? KE : KTOT;
    const __half* __restrict__ A   = ext ? g_Zext : g_Z;
    const __half* __restrict__ Bhi = ext ? g_Wext_hi : g_Whi;
    const __half* __restrict__ Blo = ext ? g_Wext_lo : g_Wlo;

    const int m_base = (wid >> 2) * 64;   // 4 warps along M
    const int n_base = (wid & 3) * 32;    // 4 warps along N

    auto load_stage = [&](int kt) {
        uint32_t sb = sbase + (uint32_t)(kt % 3) * STG_BYTES;
        int kb = ks + kt * BK;
        // A: 256 rows x 128B -> 2048 chunks, 4 per thread
#pragma unroll
        for (int i = 0; i < 4; i++) {
            int t = tid + i * 512;
            int row = t >> 3, ch = t & 7;
            uint32_t sw = (uint32_t)row * 128 + ((ch ^ (row & 7)) << 4);
            cp16(sb + OFF_A + sw, A + (size_t)(m0 + row) * kstr + kb + ch * 8);
        }
        // B hi/lo: 128 rows x 128B each -> 1024 chunks, 2 per thread each
#pragma unroll
        for (int i = 0; i < 2; i++) {
            int t = tid + i * 512;
            int row = t >> 3, ch = t & 7;
            uint32_t sw = (uint32_t)row * 128 + ((ch ^ (row & 7)) << 4);
            size_t gb = (size_t)(n0 + row) * kstr + kb + ch * 8;
            cp16(sb + OFF_BHI + sw, Bhi + gb);
            cp16(sb + OFF_BLO + sw, Blo + gb);
        }
    };

    float acc[4][4][4];
#pragma unroll
    for (int i = 0; i < 4; i++)
#pragma unroll
        for (int j = 0; j < 4; j++)
#pragma unroll
            for (int q = 0; q < 4; q++) acc[i][j][q] = 0.0f;

    const int arow_base = m_base + (lane & 15);
    const int asel = lane >> 4;
    const int brow_base = n_base + ((lane >> 4) << 3) + (lane & 7);
    const int bsel = (lane >> 3) & 1;

    load_stage(0); CP_COMMIT();
    load_stage(1); CP_COMMIT();

    for (int kt = 0; kt < nst; kt++) {
        CP_WAIT(1);            // stage kt arrived
        __syncthreads();       // all warps done with stage kt-1, see stage kt
        if (kt + 2 < nst) load_stage(kt + 2);
        CP_COMMIT();

        uint32_t sb = sbase + (uint32_t)(kt % 3) * STG_BYTES;

#pragma unroll
        for (int kk = 0; kk < 4; kk++) {
            uint32_t a[4][4], bh[2][4], bl[2][4];
#pragma unroll
            for (int mf = 0; mf < 4; mf++) {
                int row = arow_base + mf * 16;
                int ch = 2 * kk + asel;
                uint32_t ad = sb + OFF_A + row * 128 + ((ch ^ (row & 7)) << 4);
                LDSM4(a[mf][0], a[mf][1], a[mf][2], a[mf][3], ad);
            }
#pragma unroll
            for (int np = 0; np < 2; np++) {
                int row = brow_base + np * 16;
                int ch = 2 * kk + bsel;
                uint32_t boff = row * 128 + ((ch ^ (row & 7)) << 4);
                LDSM4(bh[np][0], bh[np][1], bh[np][2], bh[np][3], sb + OFF_BHI + boff);
                LDSM4(bl[np][0], bl[np][1], bl[np][2], bl[np][3], sb + OFF_BLO + boff);
            }
#pragma unroll
            for (int mf = 0; mf < 4; mf++)
#pragma unroll
                for (int np = 0; np < 2; np++) {
                    MMA16816(acc[mf][2 * np], a[mf], bh[np][0], bh[np][1]);
                    MMA16816(acc[mf][2 * np + 1], a[mf], bh[np][2], bh[np][3]);
                }
#pragma unroll
            for (int mf = 0; mf < 4; mf++)
#pragma unroll
                for (int np = 0; np < 2; np++) {
                    MMA16816(acc[mf][2 * np], a[mf], bl[np][0], bl[np][1]);
                    MMA16816(acc[mf][2 * np + 1], a[mf], bl[np][2], bl[np][3]);
                }
        }
    }
    CP_WAIT(0);

    float* dst = g_part + (size_t)z * (BATCH * ODIM);
#pragma unroll
    for (int mf = 0; mf < 4; mf++) {
#pragma unroll
        for (int nf = 0; nf < 4; nf++) {
            int m = m0 + m_base + mf * 16 + (lane >> 2);
            int o = n0 + n_base + nf * 8 + (lane & 3) * 2;
            float2 v0 = make_float2(acc[mf][nf][0], acc[mf][nf][1]);
            float2 v1 = make_float2(acc[mf][nf][2], acc[mf][nf][3]);
            *(float2*)(dst + (size_t)m * ODIM + o) = v0;
            *(float2*)(dst + (size_t)(m + 8) * ODIM + o) = v1;
        }
    }
}

// ------------------------- split-K reduction + bias --------------------------
__global__ void reduce_kernel(const float* __restrict__ base_bias,
                              const float* __restrict__ b2,
                              float* __restrict__ out) {
    int b = blockIdx.x, o = threadIdx.x;
    float acc = base_bias[o] + b2[IO + o];
#pragma unroll
    for (int s = 0; s < NSLICES_ALL; s++)
        acc += g_part[((size_t)s * BATCH + b) * ODIM + o];
    out[b * ODIM + o] = acc;
}

// ------------------------- launcher -----------------------------------------
extern "C" void kernel_launch(void* const* d_in, const int* in_sizes, int n_in,
                              void* d_out, int out_size) {
    const float* x    = (const float*)d_in[0];
    const float* cond = (const float*)d_in[1];
    const float* bw   = (const float*)d_in[2];
    const float* bb   = (const float*)d_in[3];
    const float* w1   = (const float*)d_in[4];
    const float* b1   = (const float*)d_in[5];
    const float* w2   = (const float*)d_in[6];
    const float* b2   = (const float*)d_in[7];
    float* out = (float*)d_out;

    cudaFuncSetAttribute(gemm_hmma_kernel,
                         cudaFuncAttributeMaxDynamicSharedMemorySize, SMEM_TOTAL);

    prep_h_kernel<<<256, 256>>>(cond, w1, b1);
    prep_Z_kernel<<<8192 + 768, 256>>>(x);
    prep_W_kernel<<<dim3(1024 + KE / 32, ODIM / 32), 256>>>(w2, bw, b2);
    gemm_hmma_kernel<<<dim3(ODIM / BN, BATCH / BM, NSLICES_ALL), 512, SMEM_TOTAL>>>();
    reduce_kernel<<<BATCH, 256>>>(bb, b2, out);
}

// round 8
// speedup vs baseline: 3.2051x; 1.2945x over previous
#include <cuda_runtime.h>
#include <cuda_fp16.h>
#include <cstdint>

#define BATCH 512
#define IDIM 256
#define ODIM 256
#define CDIM 128
#define HDIM 128
#define IO (IDIM * ODIM)        // 65536
#define W2COLS (IO + ODIM)      // 65792
#define KTOT (HDIM * IDIM)      // 32768
#define KE 384                  // extended K: 256 (x/base) + 128 (h/biascols)
#define NSLICE 36               // main K slices over 512 BK-units: 8x15 + 28x14
#define NSLICES_ALL (NSLICE + 1)
#define BM 256
#define BN 128
#define BK 64
#define NST_EXT (KE / BK)       // 6

// ------------------------- device scratch (no allocs) -----------------------
__device__ float g_hT[HDIM * BATCH];                        // [h][b]
__device__ float g_hB[BATCH * HDIM];                        // [b][h]
__device__ __half g_Z[(size_t)BATCH * KTOT];                // 32 MB, [b][k]
__device__ __half g_W[(size_t)ODIM * KTOT];                 // 16 MB, [o][k]
__device__ __half g_Zext[(size_t)BATCH * KE];
__device__ __half g_Wext[(size_t)ODIM * KE];
__device__ float g_part[(size_t)NSLICES_ALL * BATCH * ODIM];

// ------------------------- PTX helpers --------------------------------------
__device__ __forceinline__ uint32_t smem_u32(const void* p) {
    uint32_t a;
    asm("{ .reg .u64 t; cvta.to.shared.u64 t, %1; cvt.u32.u64 %0, t; }"
        : "=r"(a) : "l"(p));
    return a;
}
__device__ __forceinline__ void cp16(uint32_t s, const void* g) {
    asm volatile("cp.async.cg.shared.global [%0], [%1], 16;" :: "r"(s), "l"(g));
}
#define CP_COMMIT() asm volatile("cp.async.commit_group;" ::: "memory")
#define CP_WAIT(n)  asm volatile("cp.async.wait_group %0;" :: "n"(n) : "memory")

#define LDSM4(r0, r1, r2, r3, addr) \
    asm volatile("ldmatrix.sync.aligned.m8n8.x4.shared.b16 {%0,%1,%2,%3}, [%4];" \
        : "=r"(r0), "=r"(r1), "=r"(r2), "=r"(r3) : "r"(addr))

#define MMA16816(c, a, b0, b1) \
    asm volatile("mma.sync.aligned.m16n8k16.row.col.f32.f16.f16.f32 " \
        "{%0,%1,%2,%3}, {%4,%5,%6,%7}, {%8,%9}, {%0,%1,%2,%3};" \
        : "+f"((c)[0]), "+f"((c)[1]), "+f"((c)[2]), "+f"((c)[3]) \
        : "r"((a)[0]), "r"((a)[1]), "r"((a)[2]), "r"((a)[3]), "r"(b0), "r"(b1))

// ------------------------- prep kernels -------------------------------------
__global__ void prep_h_kernel(const float* __restrict__ cond,
                              const float* __restrict__ w1,
                              const float* __restrict__ b1) {
    int idx = blockIdx.x * blockDim.x + threadIdx.x;
    int b = idx >> 7, j = idx & 127;
    float acc = b1[j];
    const float* c = cond + b * CDIM;
#pragma unroll 8
    for (int k = 0; k < CDIM; k++) acc = fmaf(c[k], w1[k * HDIM + j], acc);
    float r = fmaxf(acc, 0.0f);
    g_hT[j * BATCH + b] = r;
    g_hB[b * HDIM + j] = r;
}

// Z[b][k] = fp16( h[b][k>>8] * x[b][k&255] ); blocks >= 8192 fill Zext = [x|h].
__global__ void prep_Z_kernel(const float* __restrict__ x) {
    if (blockIdx.x < 8192) {
        int c = blockIdx.x * blockDim.x + threadIdx.x;   // 0..2097151
        int b = c >> 12;
        int rem = c & 4095;
        int hh = rem >> 5;
        int i0 = (rem & 31) * 8;
        float h = g_hT[hh * BATCH + b];
        float4 x0 = *(const float4*)(x + b * IDIM + i0);
        float4 x1 = *(const float4*)(x + b * IDIM + i0 + 4);
        float z[8] = {h*x0.x, h*x0.y, h*x0.z, h*x0.w, h*x1.x, h*x1.y, h*x1.z, h*x1.w};
        union { __half e[8]; uint4 v; } o;
#pragma unroll
        for (int j = 0; j < 8; j++) o.e[j] = __float2half_rn(z[j]);
        size_t g = ((size_t)b * KTOT + (size_t)hh * 256 + i0) / 8;
        ((uint4*)g_Z)[g] = o.v;
    } else {
        int idx = (blockIdx.x - 8192) * blockDim.x + threadIdx.x;  // 0..196607
        int b = idx / KE, k = idx - b * KE;
        float v = (k < 256) ? x[b * IDIM + k] : g_hB[b * HDIM + (k - 256)];
        g_Zext[b * KE + k] = __float2half_rn(v);
    }
}

// W'[o][k] transpose to fp16; bx >= 1024 handles the Wext slice.
__global__ void prep_W_kernel(const float* __restrict__ w2,
                              const float* __restrict__ baseW,
                              const float* __restrict__ b2) {
    __shared__ float ts[32][33];
    bool ext = (blockIdx.x >= 1024);
    int kt = (ext ? (blockIdx.x - 1024) : blockIdx.x) * 32;
    int ot = blockIdx.y * 32;
    int tx = threadIdx.x & 31, ty = threadIdx.x >> 5;   // ty: 0..7
#pragma unroll
    for (int r = 0; r < 4; r++) {
        int k = kt + ty + 8 * r;
        float v;
        if (!ext) {
            v = w2[(size_t)256 * (k + (k >> 8)) + ot + tx];
        } else if (k < 256) {
            v = baseW[k * ODIM + ot + tx] + b2[k * ODIM + ot + tx];
        } else {
            v = w2[(size_t)(k - 256) * W2COLS + IO + ot + tx];
        }
        ts[ty + 8 * r][tx] = v;
    }
    __syncthreads();
#pragma unroll
    for (int r = 0; r < 4; r++) {
        int o = ot + ty + 8 * r;
        __half hv = __float2half_rn(ts[tx][ty + 8 * r]);
        if (!ext) g_W[(size_t)o * KTOT + kt + tx] = hv;
        else      g_Wext[(size_t)o * KE + kt + tx] = hv;
    }
}

// ------------------------- HMMA GEMM (mma.sync fp16, 1-term) ----------------
// C = Z@W^T. BM=256 x BN=128, 512 threads (16 warps, 4m x 4n), BK=64,
// 4-stage cp.async pipeline (192 KB). grid 2x2x37 = 148 CTAs (one per SM).
// K split: 512 BK-units = 8 slices x15 + 28 slices x14, + 1 ext slice (6).
#define STG_BYTES 49152
#define OFF_A 0
#define OFF_B 32768
#define SMEM_TOTAL (4 * STG_BYTES)   // 192 KB

__global__ void __launch_bounds__(512, 1)
gemm_hmma_kernel() {
    extern __shared__ char smem[];
    const uint32_t sbase = smem_u32(smem);
    const int tid = threadIdx.x;
    const int wid = tid >> 5, lane = tid & 31;
    const int n0 = blockIdx.x * BN;
    const int m0 = blockIdx.y * BM;
    const int z = blockIdx.z;

    const bool ext = (z == NSLICE);
    const int nst = ext ? NST_EXT : (14 + (z < 8 ? 1 : 0));
    const int ks = ext ? 0 : (14 * z + min(z, 8)) * BK;
    const size_t kstr = ext ? KE : KTOT;
    const __half* __restrict__ A = ext ? g_Zext : g_Z;
    const __half* __restrict__ B = ext ? g_Wext : g_W;

    const int m_base = (wid >> 2) * 64;   // 4 warps along M
    const int n_base = (wid & 3) * 32;    // 4 warps along N

    auto load_stage = [&](int kt) {
        uint32_t sb = sbase + (uint32_t)(kt & 3) * STG_BYTES;
        int kb = ks + kt * BK;
        // A: 256 rows x 128B -> 2048 chunks, 4 per thread
#pragma unroll
        for (int i = 0; i < 4; i++) {
            int t = tid + i * 512;
            int row = t >> 3, ch = t & 7;
            uint32_t sw = (uint32_t)row * 128 + ((ch ^ (row & 7)) << 4);
            cp16(sb + OFF_A + sw, A + (size_t)(m0 + row) * kstr + kb + ch * 8);
        }
        // B: 128 rows x 128B -> 1024 chunks, 2 per thread
#pragma unroll
        for (int i = 0; i < 2; i++) {
            int t = tid + i * 512;
            int row = t >> 3, ch = t & 7;
            uint32_t sw = (uint32_t)row * 128 + ((ch ^ (row & 7)) << 4);
            cp16(sb + OFF_B + sw, B + (size_t)(n0 + row) * kstr + kb + ch * 8);
        }
    };

    float acc[4][4][4];
#pragma unroll
    for (int i = 0; i < 4; i++)
#pragma unroll
        for (int j = 0; j < 4; j++)
#pragma unroll
            for (int q = 0; q < 4; q++) acc[i][j][q] = 0.0f;

    const int arow_base = m_base + (lane & 15);
    const int asel = lane >> 4;
    const int brow_base = n_base + ((lane >> 4) << 3) + (lane & 7);
    const int bsel = (lane >> 3) & 1;

    load_stage(0); CP_COMMIT();
    load_stage(1); CP_COMMIT();
    load_stage(2); CP_COMMIT();

    for (int kt = 0; kt < nst; kt++) {
        CP_WAIT(2);            // stage kt arrived
        __syncthreads();       // all warps done with stage kt-3 buf, see stage kt
        if (kt + 3 < nst) load_stage(kt + 3);
        CP_COMMIT();

        uint32_t sb = sbase + (uint32_t)(kt & 3) * STG_BYTES;

#pragma unroll
        for (int kk = 0; kk < 4; kk++) {
            uint32_t a[4][4], bh[2][4];
#pragma unroll
            for (int mf = 0; mf < 4; mf++) {
                int row = arow_base + mf * 16;
                int ch = 2 * kk + asel;
                uint32_t ad = sb + OFF_A + row * 128 + ((ch ^ (row & 7)) << 4);
                LDSM4(a[mf][0], a[mf][1], a[mf][2], a[mf][3], ad);
            }
#pragma unroll
            for (int np = 0; np < 2; np++) {
                int row = brow_base + np * 16;
                int ch = 2 * kk + bsel;
                uint32_t boff = row * 128 + ((ch ^ (row & 7)) << 4);
                LDSM4(bh[np][0], bh[np][1], bh[np][2], bh[np][3], sb + OFF_B + boff);
            }
#pragma unroll
            for (int mf = 0; mf < 4; mf++)
#pragma unroll
                for (int np = 0; np < 2; np++) {
                    MMA16816(acc[mf][2 * np], a[mf], bh[np][0], bh[np][1]);
                    MMA16816(acc[mf][2 * np + 1], a[mf], bh[np][2], bh[np][3]);
                }
        }
    }
    CP_WAIT(0);

    float* dst = g_part + (size_t)z * (BATCH * ODIM);
#pragma unroll
    for (int mf = 0; mf < 4; mf++) {
#pragma unroll
        for (int nf = 0; nf < 4; nf++) {
            int m = m0 + m_base + mf * 16 + (lane >> 2);
            int o = n0 + n_base + nf * 8 + (lane & 3) * 2;
            float2 v0 = make_float2(acc[mf][nf][0], acc[mf][nf][1]);
            float2 v1 = make_float2(acc[mf][nf][2], acc[mf][nf][3]);
            *(float2*)(dst + (size_t)m * ODIM + o) = v0;
            *(float2*)(dst + (size_t)(m + 8) * ODIM + o) = v1;
        }
    }
}

// ------------------------- split-K reduction + bias --------------------------
__global__ void reduce_kernel(const float* __restrict__ base_bias,
                              const float* __restrict__ b2,
                              float* __restrict__ out) {
    int b = blockIdx.x, o = threadIdx.x;
    float acc = base_bias[o] + b2[IO + o];
#pragma unroll
    for (int s = 0; s < NSLICES_ALL; s++)
        acc += g_part[((size_t)s * BATCH + b) * ODIM + o];
    out[b * ODIM + o] = acc;
}

// ------------------------- launcher -----------------------------------------
extern "C" void kernel_launch(void* const* d_in, const int* in_sizes, int n_in,
                              void* d_out, int out_size) {
    const float* x    = (const float*)d_in[0];
    const float* cond = (const float*)d_in[1];
    const float* bw   = (const float*)d_in[2];
    const float* bb   = (const float*)d_in[3];
    const float* w1   = (const float*)d_in[4];
    const float* b1   = (const float*)d_in[5];
    const float* w2   = (const float*)d_in[6];
    const float* b2   = (const float*)d_in[7];
    float* out = (float*)d_out;

    cudaFuncSetAttribute(gemm_hmma_kernel,
                         cudaFuncAttributeMaxDynamicSharedMemorySize, SMEM_TOTAL);

    prep_h_kernel<<<256, 256>>>(cond, w1, b1);
    prep_Z_kernel<<<8192 + 768, 256>>>(x);
    prep_W_kernel<<<dim3(1024 + KE / 32, ODIM / 32), 256>>>(w2, bw, b2);
    gemm_hmma_kernel<<<dim3(ODIM / BN, BATCH / BM, NSLICES_ALL), 512, SMEM_TOTAL>>>();
    reduce_kernel<<<BATCH, 256>>>(bb, b2, out);
}

// round 9
// speedup vs baseline: 3.4488x; 1.0761x over previous
#include <cuda_runtime.h>
#include <cuda_fp16.h>
#include <cstdint>

#define BATCH 512
#define IDIM 256
#define ODIM 256
#define CDIM 128
#define HDIM 128
#define IO (IDIM * ODIM)        // 65536
#define W2COLS (IO + ODIM)      // 65792
#define KTOT (HDIM * IDIM)      // 32768
#define KE 384                  // extended K: 256 (x/base) + 128 (h/biascols)
#define NSLICES 37              // 36 x (14 main BK) + 1 x (8 main + 6 ext BK)
#define BM 256
#define BN 128
#define BK 64
#define NST 14                  // stages per slice (uniform)

// ------------------------- device scratch (no allocs) -----------------------
__device__ __half g_Z[(size_t)BATCH * KTOT];                // 32 MB, [b][k]
__device__ __half g_W[(size_t)ODIM * KTOT];                 // 16 MB, [o][k]
__device__ __half g_Zext[(size_t)BATCH * KE];
__device__ __half g_Wext[(size_t)ODIM * KE];
__device__ float g_part[(size_t)NSLICES * BATCH * ODIM];

// ------------------------- PTX helpers --------------------------------------
__device__ __forceinline__ uint32_t smem_u32(const void* p) {
    uint32_t a;
    asm("{ .reg .u64 t; cvta.to.shared.u64 t, %1; cvt.u32.u64 %0, t; }"
        : "=r"(a) : "l"(p));
    return a;
}
__device__ __forceinline__ void cp16(uint32_t s, const void* g) {
    asm volatile("cp.async.cg.shared.global [%0], [%1], 16;" :: "r"(s), "l"(g));
}
#define CP_COMMIT() asm volatile("cp.async.commit_group;" ::: "memory")
#define CP_WAIT(n)  asm volatile("cp.async.wait_group %0;" :: "n"(n) : "memory")

#define LDSM4(r0, r1, r2, r3, addr) \
    asm volatile("ldmatrix.sync.aligned.m8n8.x4.shared.b16 {%0,%1,%2,%3}, [%4];" \
        : "=r"(r0), "=r"(r1), "=r"(r2), "=r"(r3) : "r"(addr))

#define MMA16816(c, a, b0, b1) \
    asm volatile("mma.sync.aligned.m16n8k16.row.col.f32.f16.f16.f32 " \
        "{%0,%1,%2,%3}, {%4,%5,%6,%7}, {%8,%9}, {%0,%1,%2,%3};" \
        : "+f"((c)[0]), "+f"((c)[1]), "+f"((c)[2]), "+f"((c)[3]) \
        : "r"((a)[0]), "r"((a)[1]), "r"((a)[2]), "r"((a)[3]), "r"(b0), "r"(b1))

// ------------------------- fused prep kernel ---------------------------------
// blocks [0, 2048):      Z main   (4 blocks per batch row, h computed in-block)
// blocks [2048, 2560):   Zext     (1 block per batch row)
// blocks [2560, 10848):  W / Wext transpose + fp32->fp16
#define ZB 2048
#define ZEB 512
#define WB0 (ZB + ZEB)          // 2560
#define WBX 1036                // 1024 main k-tiles + 12 ext k-tiles
#define NBLK (WB0 + WBX * 8)    // 10848

__global__ void __launch_bounds__(256)
prep_all_kernel(const float* __restrict__ x,
                const float* __restrict__ cond,
                const float* __restrict__ w1,
                const float* __restrict__ b1,
                const float* __restrict__ w2,
                const float* __restrict__ baseW,
                const float* __restrict__ b2) {
    __shared__ float cs[CDIM];
    __shared__ float hs[HDIM];
    __shared__ float xs[IDIM];
    __shared__ float ts[32][33];
    const int bid = blockIdx.x;
    const int tid = threadIdx.x;

    if (bid < ZB + ZEB) {
        // ---- compute h[b] in-block, then emit Z (or Zext) ----
        const bool zext = (bid >= ZB);
        const int b = zext ? (bid - ZB) : (bid >> 2);
        if (tid < CDIM) cs[tid] = cond[b * CDIM + tid];
        xs[tid] = x[b * IDIM + tid];
        __syncthreads();
        if (tid < HDIM) {
            float acc = b1[tid];
#pragma unroll 8
            for (int k = 0; k < CDIM; k++)
                acc = fmaf(cs[k], w1[k * HDIM + tid], acc);
            hs[tid] = fmaxf(acc, 0.0f);
        }
        __syncthreads();
        if (!zext) {
            // 4 uint4-chunks (32 halves) per thread; 1024 chunks per block
#pragma unroll
            for (int r = 0; r < 4; r++) {
                int chunk = (bid & 3) * 1024 + r * 256 + tid;
                int k0 = chunk * 8;
                float h = hs[k0 >> 8];
                const float* xr = xs + (k0 & 255);
                union { __half e[8]; uint4 v; } o;
#pragma unroll
                for (int j = 0; j < 8; j++) o.e[j] = __float2half_rn(h * xr[j]);
                ((uint4*)g_Z)[(size_t)b * (KTOT / 8) + chunk] = o.v;
            }
        } else {
            g_Zext[b * KE + tid] = __float2half_rn(xs[tid]);
            if (tid < HDIM) g_Zext[b * KE + 256 + tid] = __float2half_rn(hs[tid]);
        }
    } else {
        // ---- W transpose: wb = bid - WB0 -> (bx, by) of old (1036, 8) grid ----
        int wb = bid - WB0;
        int bx = wb % WBX, by = wb / WBX;
        bool ext = (bx >= 1024);
        int kt = (ext ? (bx - 1024) : bx) * 32;
        int ot = by * 32;
        int tx = tid & 31, ty = tid >> 5;   // ty: 0..7
#pragma unroll
        for (int r = 0; r < 4; r++) {
            int k = kt + ty + 8 * r;
            float v;
            if (!ext) {
                v = w2[(size_t)256 * (k + (k >> 8)) + ot + tx];
            } else if (k < 256) {
                v = baseW[k * ODIM + ot + tx] + b2[k * ODIM + ot + tx];
            } else {
                v = w2[(size_t)(k - 256) * W2COLS + IO + ot + tx];
            }
            ts[ty + 8 * r][tx] = v;
        }
        __syncthreads();
#pragma unroll
        for (int r = 0; r < 4; r++) {
            int o = ot + ty + 8 * r;
            __half hv = __float2half_rn(ts[tx][ty + 8 * r]);
            if (!ext) g_W[(size_t)o * KTOT + kt + tx] = hv;
            else      g_Wext[(size_t)o * KE + kt + tx] = hv;
        }
    }
}

// ------------------------- HMMA GEMM (mma.sync fp16, 1-term) ----------------
// C = Z@W^T (+ ext). BM=256 x BN=128, 512 threads (16 warps, 4m x 4n), BK=64,
// 4-stage cp.async pipeline (192 KB). grid 2x2x37 = 148 CTAs (one per SM).
// Slices 0..35: 14 main BK-units each. Slice 36: main units 504..511 (8) then
// the 6 ext BK-units -> every CTA runs exactly 14 stages.
#define STG_BYTES 49152
#define OFF_A 0
#define OFF_B 32768
#define SMEM_TOTAL (4 * STG_BYTES)   // 192 KB

__global__ void __launch_bounds__(512, 1)
gemm_hmma_kernel() {
    extern __shared__ char smem[];
    const uint32_t sbase = smem_u32(smem);
    const int tid = threadIdx.x;
    const int wid = tid >> 5, lane = tid & 31;
    const int n0 = blockIdx.x * BN;
    const int m0 = blockIdx.y * BM;
    const int z = blockIdx.z;
    const bool mixed = (z == NSLICES - 1);

    const int m_base = (wid >> 2) * 64;   // 4 warps along M
    const int n_base = (wid & 3) * 32;    // 4 warps along N

    auto load_stage = [&](int kt) {
        uint32_t sb = sbase + (uint32_t)(kt & 3) * STG_BYTES;
        const __half* A;
        const __half* B;
        size_t kstr;
        int kb;
        if (!mixed || kt < 8) {
            A = g_Z; B = g_W; kstr = KTOT;
            kb = (z * NST + kt) * BK;          // z=36,kt<8 -> units 504..511
        } else {
            A = g_Zext; B = g_Wext; kstr = KE;
            kb = (kt - 8) * BK;
        }
        // A: 256 rows x 128B -> 2048 chunks, 4 per thread
#pragma unroll
        for (int i = 0; i < 4; i++) {
            int t = tid + i * 512;
            int row = t >> 3, ch = t & 7;
            uint32_t sw = (uint32_t)row * 128 + ((ch ^ (row & 7)) << 4);
            cp16(sb + OFF_A + sw, A + (size_t)(m0 + row) * kstr + kb + ch * 8);
        }
        // B: 128 rows x 128B -> 1024 chunks, 2 per thread
#pragma unroll
        for (int i = 0; i < 2; i++) {
            int t = tid + i * 512;
            int row = t >> 3, ch = t & 7;
            uint32_t sw = (uint32_t)row * 128 + ((ch ^ (row & 7)) << 4);
            cp16(sb + OFF_B + sw, B + (size_t)(n0 + row) * kstr + kb + ch * 8);
        }
    };

    float acc[4][4][4];
#pragma unroll
    for (int i = 0; i < 4; i++)
#pragma unroll
        for (int j = 0; j < 4; j++)
#pragma unroll
            for (int q = 0; q < 4; q++) acc[i][j][q] = 0.0f;

    const int arow_base = m_base + (lane & 15);
    const int asel = lane >> 4;
    const int brow_base = n_base + ((lane >> 4) << 3) + (lane & 7);
    const int bsel = (lane >> 3) & 1;

    load_stage(0); CP_COMMIT();
    load_stage(1); CP_COMMIT();
    load_stage(2); CP_COMMIT();

    for (int kt = 0; kt < NST; kt++) {
        CP_WAIT(2);            // stage kt arrived
        __syncthreads();       // all warps done with this buffer's prior use
        if (kt + 3 < NST) load_stage(kt + 3);
        CP_COMMIT();

        uint32_t sb = sbase + (uint32_t)(kt & 3) * STG_BYTES;

#pragma unroll
        for (int kk = 0; kk < 4; kk++) {
            uint32_t a[4][4], bh[2][4];
#pragma unroll
            for (int mf = 0; mf < 4; mf++) {
                int row = arow_base + mf * 16;
                int ch = 2 * kk + asel;
                uint32_t ad = sb + OFF_A + row * 128 + ((ch ^ (row & 7)) << 4);
                LDSM4(a[mf][0], a[mf][1], a[mf][2], a[mf][3], ad);
            }
#pragma unroll
            for (int np = 0; np < 2; np++) {
                int row = brow_base + np * 16;
                int ch = 2 * kk + bsel;
                uint32_t boff = row * 128 + ((ch ^ (row & 7)) << 4);
                LDSM4(bh[np][0], bh[np][1], bh[np][2], bh[np][3], sb + OFF_B + boff);
            }
#pragma unroll
            for (int mf = 0; mf < 4; mf++)
#pragma unroll
                for (int np = 0; np < 2; np++) {
                    MMA16816(acc[mf][2 * np], a[mf], bh[np][0], bh[np][1]);
                    MMA16816(acc[mf][2 * np + 1], a[mf], bh[np][2], bh[np][3]);
                }
        }
    }
    CP_WAIT(0);

    float* dst = g_part + (size_t)z * (BATCH * ODIM);
#pragma unroll
    for (int mf = 0; mf < 4; mf++) {
#pragma unroll
        for (int nf = 0; nf < 4; nf++) {
            int m = m0 + m_base + mf * 16 + (lane >> 2);
            int o = n0 + n_base + nf * 8 + (lane & 3) * 2;
            float2 v0 = make_float2(acc[mf][nf][0], acc[mf][nf][1]);
            float2 v1 = make_float2(acc[mf][nf][2], acc[mf][nf][3]);
            *(float2*)(dst + (size_t)m * ODIM + o) = v0;
            *(float2*)(dst + (size_t)(m + 8) * ODIM + o) = v1;
        }
    }
}

// ------------------------- split-K reduction + bias --------------------------
__global__ void reduce_kernel(const float* __restrict__ base_bias,
                              const float* __restrict__ b2,
                              float* __restrict__ out) {
    int b = blockIdx.x, o = threadIdx.x;
    float acc = base_bias[o] + b2[IO + o];
#pragma unroll
    for (int s = 0; s < NSLICES; s++)
        acc += g_part[((size_t)s * BATCH + b) * ODIM + o];
    out[b * ODIM + o] = acc;
}

// ------------------------- launcher -----------------------------------------
extern "C" void kernel_launch(void* const* d_in, const int* in_sizes, int n_in,
                              void* d_out, int out_size) {
    const float* x    = (const float*)d_in[0];
    const float* cond = (const float*)d_in[1];
    const float* bw   = (const float*)d_in[2];
    const float* bb   = (const float*)d_in[3];
    const float* w1   = (const float*)d_in[4];
    const float* b1   = (const float*)d_in[5];
    const float* w2   = (const float*)d_in[6];
    const float* b2   = (const float*)d_in[7];
    float* out = (float*)d_out;

    cudaFuncSetAttribute(gemm_hmma_kernel,
                         cudaFuncAttributeMaxDynamicSharedMemorySize, SMEM_TOTAL);

    prep_all_kernel<<<NBLK, 256>>>(x, cond, w1, b1, w2, bw, b2);
    gemm_hmma_kernel<<<dim3(ODIM / BN, BATCH / BM, NSLICES), 512, SMEM_TOTAL>>>();
    reduce_kernel<<<BATCH, 256>>>(bb, b2, out);
}

// round 10
// speedup vs baseline: 4.2316x; 1.2270x over previous
#include <cuda_runtime.h>
#include <cuda_fp16.h>
#include <cstdint>

#define BATCH 512
#define IDIM 256
#define ODIM 256
#define CDIM 128
#define HDIM 128
#define IO (IDIM * ODIM)        // 65536
#define W2COLS (IO + ODIM)      // 65792
#define KTOT (HDIM * IDIM)      // 32768
#define KE 384                  // extended K: 256 (x/base) + 128 (h/biascols)
#define NSLICES 37              // 36 x (14 main BK) + 1 x (8 main + 6 ext BK)
#define BM 256
#define BN 128
#define BK 64
#define NST 14                  // stages per slice (uniform)

// ------------------------- device scratch (no allocs) -----------------------
__device__ __half g_Z[(size_t)BATCH * KTOT];                // 32 MB, [b][k]
__device__ __half g_W[(size_t)KTOT * ODIM];                 // 16 MB, [k][o]
__device__ __half g_Zext[(size_t)BATCH * KE];
__device__ __half g_Wext[(size_t)KE * ODIM];                // [k][o]
__device__ float g_part[(size_t)NSLICES * BATCH * ODIM];

// ------------------------- PTX helpers --------------------------------------
__device__ __forceinline__ uint32_t smem_u32(const void* p) {
    uint32_t a;
    asm("{ .reg .u64 t; cvta.to.shared.u64 t, %1; cvt.u32.u64 %0, t; }"
        : "=r"(a) : "l"(p));
    return a;
}
__device__ __forceinline__ void cp16(uint32_t s, const void* g) {
    asm volatile("cp.async.cg.shared.global [%0], [%1], 16;" :: "r"(s), "l"(g));
}
#define CP_COMMIT() asm volatile("cp.async.commit_group;" ::: "memory")
#define CP_WAIT(n)  asm volatile("cp.async.wait_group %0;" :: "n"(n) : "memory")

#define LDSM4(r0, r1, r2, r3, addr) \
    asm volatile("ldmatrix.sync.aligned.m8n8.x4.shared.b16 {%0,%1,%2,%3}, [%4];" \
        : "=r"(r0), "=r"(r1), "=r"(r2), "=r"(r3) : "r"(addr))

#define LDSM4T(r0, r1, r2, r3, addr) \
    asm volatile("ldmatrix.sync.aligned.m8n8.x4.trans.shared.b16 {%0,%1,%2,%3}, [%4];" \
        : "=r"(r0), "=r"(r1), "=r"(r2), "=r"(r3) : "r"(addr))

#define MMA16816(c, a, b0, b1) \
    asm volatile("mma.sync.aligned.m16n8k16.row.col.f32.f16.f16.f32 " \
        "{%0,%1,%2,%3}, {%4,%5,%6,%7}, {%8,%9}, {%0,%1,%2,%3};" \
        : "+f"((c)[0]), "+f"((c)[1]), "+f"((c)[2]), "+f"((c)[3]) \
        : "r"((a)[0]), "r"((a)[1]), "r"((a)[2]), "r"((a)[3]), "r"(b0), "r"(b1))

// ------------------------- fused prep kernel ---------------------------------
// blocks [0, 2048):      Z main   (4 blocks per batch row, h computed in-block)
// blocks [2048, 2560):   Zext     (1 block per batch row)
// blocks [2560, 6656):   W main   (pure streaming fp32->fp16, [k][o] layout)
// blocks [6656, 6704):   Wext     (streaming, [k][o])
#define ZB 2048
#define ZEB 512
#define WB0 (ZB + ZEB)          // 2560
#define WMB 4096                // KTOT*ODIM/8/256
#define WEB 48                  // KE*ODIM/8/256
#define NBLK (WB0 + WMB + WEB)  // 6704

__global__ void __launch_bounds__(256)
prep_all_kernel(const float* __restrict__ x,
                const float* __restrict__ cond,
                const float* __restrict__ w1,
                const float* __restrict__ b1,
                const float* __restrict__ w2,
                const float* __restrict__ baseW,
                const float* __restrict__ b2) {
    __shared__ float cs[CDIM];
    __shared__ float hs[HDIM];
    __shared__ float xs[IDIM];
    const int bid = blockIdx.x;
    const int tid = threadIdx.x;

    if (bid < ZB + ZEB) {
        // ---- compute h[b] in-block, then emit Z (or Zext) ----
        const bool zext = (bid >= ZB);
        const int b = zext ? (bid - ZB) : (bid >> 2);
        if (tid < CDIM) cs[tid] = cond[b * CDIM + tid];
        xs[tid] = x[b * IDIM + tid];
        __syncthreads();
        if (tid < HDIM) {
            float acc = b1[tid];
#pragma unroll 8
            for (int k = 0; k < CDIM; k++)
                acc = fmaf(cs[k], w1[k * HDIM + tid], acc);
            hs[tid] = fmaxf(acc, 0.0f);
        }
        __syncthreads();
        if (!zext) {
#pragma unroll
            for (int r = 0; r < 4; r++) {
                int chunk = (bid & 3) * 1024 + r * 256 + tid;
                int k0 = chunk * 8;
                float h = hs[k0 >> 8];
                const float* xr = xs + (k0 & 255);
                union { __half e[8]; uint4 v; } o;
#pragma unroll
                for (int j = 0; j < 8; j++) o.e[j] = __float2half_rn(h * xr[j]);
                ((uint4*)g_Z)[(size_t)b * (KTOT / 8) + chunk] = o.v;
            }
        } else {
            g_Zext[b * KE + tid] = __float2half_rn(xs[tid]);
            if (tid < HDIM) g_Zext[b * KE + 256 + tid] = __float2half_rn(hs[tid]);
        }
    } else if (bid < WB0 + WMB) {
        // ---- W main: g_W[k][o] = fp16(w2[(k>>8)*W2COLS + (k&255)*256 + o]) ----
        int u = (bid - WB0) * 256 + tid;      // uint4 chunk id (8 halves)
        int j0 = u * 8;                        // output half index = k*256 + o
        int k = j0 >> 8;
        size_t in = (size_t)(k >> 8) * W2COLS + (size_t)(k & 255) * 256 + (j0 & 255);
        float4 v0 = *(const float4*)(w2 + in);
        float4 v1 = *(const float4*)(w2 + in + 4);
        union { __half e[8]; uint4 v; } o;
        o.e[0] = __float2half_rn(v0.x); o.e[1] = __float2half_rn(v0.y);
        o.e[2] = __float2half_rn(v0.z); o.e[3] = __float2half_rn(v0.w);
        o.e[4] = __float2half_rn(v1.x); o.e[5] = __float2half_rn(v1.y);
        o.e[6] = __float2half_rn(v1.z); o.e[7] = __float2half_rn(v1.w);
        ((uint4*)g_W)[u] = o.v;
    } else {
        // ---- Wext: [k][o], k<256: baseW+b2; k>=256: w2 bias columns ----
        int u = (bid - WB0 - WMB) * 256 + tid;
        int j0 = u * 8;
        int k = j0 >> 8, o0 = j0 & 255;
        float v[8];
        if (k < 256) {
            float4 a0 = *(const float4*)(baseW + k * ODIM + o0);
            float4 a1 = *(const float4*)(baseW + k * ODIM + o0 + 4);
            float4 c0 = *(const float4*)(b2 + k * ODIM + o0);
            float4 c1 = *(const float4*)(b2 + k * ODIM + o0 + 4);
            v[0]=a0.x+c0.x; v[1]=a0.y+c0.y; v[2]=a0.z+c0.z; v[3]=a0.w+c0.w;
            v[4]=a1.x+c1.x; v[5]=a1.y+c1.y; v[6]=a1.z+c1.z; v[7]=a1.w+c1.w;
        } else {
            const float* src = w2 + (size_t)(k - 256) * W2COLS + IO + o0;
            float4 a0 = *(const float4*)(src);
            float4 a1 = *(const float4*)(src + 4);
            v[0]=a0.x; v[1]=a0.y; v[2]=a0.z; v[3]=a0.w;
            v[4]=a1.x; v[5]=a1.y; v[6]=a1.z; v[7]=a1.w;
        }
        union { __half e[8]; uint4 v; } o;
#pragma unroll
        for (int j = 0; j < 8; j++) o.e[j] = __float2half_rn(v[j]);
        ((uint4*)g_Wext)[u] = o.v;
    }
}

// ------------------------- HMMA GEMM (mma.sync fp16, 1-term) ----------------
// C = Z@W (+ ext), W stored [k][o]. BM=256 x BN=128, 512 threads (16 warps,
// 4m x 4n), BK=64, 4-stage cp.async pipeline (192 KB). grid 2x2x37 = 148 CTAs.
// B tiles loaded [k][n] and consumed via ldmatrix.trans.
#define STG_BYTES 49152
#define OFF_A 0
#define OFF_B 32768
#define SMEM_TOTAL (4 * STG_BYTES)   // 192 KB

__global__ void __launch_bounds__(512, 1)
gemm_hmma_kernel() {
    extern __shared__ char smem[];
    const uint32_t sbase = smem_u32(smem);
    const int tid = threadIdx.x;
    const int wid = tid >> 5, lane = tid & 31;
    const int n0 = blockIdx.x * BN;
    const int m0 = blockIdx.y * BM;
    const int z = blockIdx.z;
    const bool mixed = (z == NSLICES - 1);

    const int m_base = (wid >> 2) * 64;   // 4 warps along M
    const int n_base = (wid & 3) * 32;    // 4 warps along N

    auto load_stage = [&](int kt) {
        uint32_t sb = sbase + (uint32_t)(kt & 3) * STG_BYTES;
        const __half* A;
        const __half* B;
        size_t kstrA;
        int kb;
        if (!mixed || kt < 8) {
            A = g_Z; B = g_W; kstrA = KTOT;
            kb = (z * NST + kt) * BK;
        } else {
            A = g_Zext; B = g_Wext; kstrA = KE;
            kb = (kt - 8) * BK;
        }
        // A: 256 rows x 128B -> 2048 chunks, 4 per thread
#pragma unroll
        for (int i = 0; i < 4; i++) {
            int t = tid + i * 512;
            int row = t >> 3, ch = t & 7;
            uint32_t sw = (uint32_t)row * 128 + ((ch ^ (row & 7)) << 4);
            cp16(sb + OFF_A + sw, A + (size_t)(m0 + row) * kstrA + kb + ch * 8);
        }
        // B: 64 k-rows x 256B -> 1024 chunks, 2 per thread ([k][o] layout)
#pragma unroll
        for (int i = 0; i < 2; i++) {
            int t = tid + i * 512;
            int row = t >> 4, ch = t & 15;
            uint32_t sw = (uint32_t)row * 256 + ((ch ^ (row & 7)) << 4);
            cp16(sb + OFF_B + sw, B + (size_t)(kb + row) * ODIM + n0 + ch * 8);
        }
    };

    float acc[4][4][4];
#pragma unroll
    for (int i = 0; i < 4; i++)
#pragma unroll
        for (int j = 0; j < 4; j++)
#pragma unroll
            for (int q = 0; q < 4; q++) acc[i][j][q] = 0.0f;

    const int arow_base = m_base + (lane & 15);
    const int asel = lane >> 4;
    const int brow_lane = lane & 15;          // k-row within k16 step
    const int bch_lane = (lane >> 4) & 1;     // n8 group select

    load_stage(0); CP_COMMIT();
    load_stage(1); CP_COMMIT();
    load_stage(2); CP_COMMIT();

    for (int kt = 0; kt < NST; kt++) {
        CP_WAIT(2);
        __syncthreads();
        if (kt + 3 < NST) load_stage(kt + 3);
        CP_COMMIT();

        uint32_t sb = sbase + (uint32_t)(kt & 3) * STG_BYTES;

#pragma unroll
        for (int kk = 0; kk < 4; kk++) {
            uint32_t a[4][4], bt[2][4];
#pragma unroll
            for (int mf = 0; mf < 4; mf++) {
                int row = arow_base + mf * 16;
                int ch = 2 * kk + asel;
                uint32_t ad = sb + OFF_A + row * 128 + ((ch ^ (row & 7)) << 4);
                LDSM4(a[mf][0], a[mf][1], a[mf][2], a[mf][3], ad);
            }
#pragma unroll
            for (int np = 0; np < 2; np++) {
                int row = kk * 16 + brow_lane;
                int ch = (n_base >> 3) + np * 2 + bch_lane;
                uint32_t bd = sb + OFF_B + row * 256 + ((ch ^ (row & 7)) << 4);
                LDSM4T(bt[np][0], bt[np][1], bt[np][2], bt[np][3], bd);
            }
#pragma unroll
            for (int mf = 0; mf < 4; mf++)
#pragma unroll
                for (int np = 0; np < 2; np++) {
                    MMA16816(acc[mf][2 * np], a[mf], bt[np][0], bt[np][1]);
                    MMA16816(acc[mf][2 * np + 1], a[mf], bt[np][2], bt[np][3]);
                }
        }
    }
    CP_WAIT(0);

    float* dst = g_part + (size_t)z * (BATCH * ODIM);
#pragma unroll
    for (int mf = 0; mf < 4; mf++) {
#pragma unroll
        for (int nf = 0; nf < 4; nf++) {
            int m = m0 + m_base + mf * 16 + (lane >> 2);
            int o = n0 + n_base + nf * 8 + (lane & 3) * 2;
            float2 v0 = make_float2(acc[mf][nf][0], acc[mf][nf][1]);
            float2 v1 = make_float2(acc[mf][nf][2], acc[mf][nf][3]);
            *(float2*)(dst + (size_t)m * ODIM + o) = v0;
            *(float2*)(dst + (size_t)(m + 8) * ODIM + o) = v1;
        }
    }
}

// ------------------------- split-K reduction + bias --------------------------
__global__ void reduce_kernel(const float* __restrict__ base_bias,
                              const float* __restrict__ b2,
                              float* __restrict__ out) {
    int b = blockIdx.x, o = threadIdx.x;
    float acc = base_bias[o] + b2[IO + o];
#pragma unroll
    for (int s = 0; s < NSLICES; s++)
        acc += g_part[((size_t)s * BATCH + b) * ODIM + o];
    out[b * ODIM + o] = acc;
}

// ------------------------- launcher -----------------------------------------
extern "C" void kernel_launch(void* const* d_in, const int* in_sizes, int n_in,
                              void* d_out, int out_size) {
    const float* x    = (const float*)d_in[0];
    const float* cond = (const float*)d_in[1];
    const float* bw   = (const float*)d_in[2];
    const float* bb   = (const float*)d_in[3];
    const float* w1   = (const float*)d_in[4];
    const float* b1   = (const float*)d_in[5];
    const float* w2   = (const float*)d_in[6];
    const float* b2   = (const float*)d_in[7];
    float* out = (float*)d_out;

    cudaFuncSetAttribute(gemm_hmma_kernel,
                         cudaFuncAttributeMaxDynamicSharedMemorySize, SMEM_TOTAL);

    prep_all_kernel<<<NBLK, 256>>>(x, cond, w1, b1, w2, bw, b2);
    gemm_hmma_kernel<<<dim3(ODIM / BN, BATCH / BM, NSLICES), 512, SMEM_TOTAL>>>();
    reduce_kernel<<<BATCH, 256>>>(bb, b2, out);
}

// round 11
// speedup vs baseline: 4.6969x; 1.1100x over previous
#include <cuda_runtime.h>
#include <cuda_fp16.h>
#include <cstdint>

#define BATCH 512
#define IDIM 256
#define ODIM 256
#define CDIM 128
#define HDIM 128
#define IO (IDIM * ODIM)        // 65536
#define W2COLS (IO + ODIM)      // 65792
#define KTOT (HDIM * IDIM)      // 32768
#define KE 384                  // extended K: 256 (x/base) + 128 (h/biascols)
#define NSLICES 37              // 36 x (14 main BK) + 1 x (8 main + 6 ext BK)
#define BM 256
#define BN 128
#define BK 64
#define NST 14                  // stages per slice (uniform)

// ------------------------- device scratch (no allocs) -----------------------
__device__ __half g_Z[(size_t)BATCH * KTOT];                // 32 MB, [b][k]
__device__ __half g_W[(size_t)KTOT * ODIM];                 // 16 MB, [k][o]
__device__ __half g_Zext[(size_t)BATCH * KE];
__device__ __half g_Wext[(size_t)KE * ODIM];                // [k][o]
__device__ float g_part[(size_t)NSLICES * BATCH * ODIM];

// ------------------------- PTX helpers --------------------------------------
__device__ __forceinline__ uint32_t smem_u32(const void* p) {
    uint32_t a;
    asm("{ .reg .u64 t; cvta.to.shared.u64 t, %1; cvt.u32.u64 %0, t; }"
        : "=r"(a) : "l"(p));
    return a;
}
__device__ __forceinline__ void cp16(uint32_t s, const void* g) {
    asm volatile("cp.async.cg.shared.global [%0], [%1], 16;" :: "r"(s), "l"(g));
}
#define CP_COMMIT() asm volatile("cp.async.commit_group;" ::: "memory")
#define CP_WAIT(n)  asm volatile("cp.async.wait_group %0;" :: "n"(n) : "memory")

#define LDSM4(r0, r1, r2, r3, addr) \
    asm volatile("ldmatrix.sync.aligned.m8n8.x4.shared.b16 {%0,%1,%2,%3}, [%4];" \
        : "=r"(r0), "=r"(r1), "=r"(r2), "=r"(r3) : "r"(addr))

#define LDSM4T(r0, r1, r2, r3, addr) \
    asm volatile("ldmatrix.sync.aligned.m8n8.x4.trans.shared.b16 {%0,%1,%2,%3}, [%4];" \
        : "=r"(r0), "=r"(r1), "=r"(r2), "=r"(r3) : "r"(addr))

#define MMA16816(c, a, b0, b1) \
    asm volatile("mma.sync.aligned.m16n8k16.row.col.f32.f16.f16.f32 " \
        "{%0,%1,%2,%3}, {%4,%5,%6,%7}, {%8,%9}, {%0,%1,%2,%3};" \
        : "+f"((c)[0]), "+f"((c)[1]), "+f"((c)[2]), "+f"((c)[3]) \
        : "r"((a)[0]), "r"((a)[1]), "r"((a)[2]), "r"((a)[3]), "r"(b0), "r"(b1))

// ------------------------- fused prep kernel ---------------------------------
// blocks [0, 512):       one block per batch row: h once, Z main + Zext
// blocks [512, 4608):    W main (pure streaming fp32->fp16, [k][o] layout)
// blocks [4608, 4656):   Wext (streaming, [k][o])
#define ZB 512
#define WMB 4096                // KTOT*ODIM/8/256
#define WEB 48                  // KE*ODIM/8/256
#define NBLK (ZB + WMB + WEB)   // 4656

__global__ void __launch_bounds__(256)
prep_all_kernel(const float* __restrict__ x,
                const float* __restrict__ cond,
                const float* __restrict__ w1,
                const float* __restrict__ b1,
                const float* __restrict__ w2,
                const float* __restrict__ baseW,
                const float* __restrict__ b2) {
    __shared__ float cs[CDIM];
    __shared__ float hs[HDIM];
    __shared__ float xs[IDIM];
    const int bid = blockIdx.x;
    const int tid = threadIdx.x;

    if (bid < ZB) {
        // ---- one block per batch row b ----
        const int b = bid;
        if (tid < CDIM) cs[tid] = cond[b * CDIM + tid];
        xs[tid] = x[b * IDIM + tid];
        __syncthreads();
        if (tid < HDIM) {
            // 4-way split accumulation to shorten the dependency chain
            float a0 = b1[tid], a1 = 0.f, a2 = 0.f, a3 = 0.f;
#pragma unroll 8
            for (int k = 0; k < CDIM; k += 4) {
                a0 = fmaf(cs[k],     w1[(k)     * HDIM + tid], a0);
                a1 = fmaf(cs[k + 1], w1[(k + 1) * HDIM + tid], a1);
                a2 = fmaf(cs[k + 2], w1[(k + 2) * HDIM + tid], a2);
                a3 = fmaf(cs[k + 3], w1[(k + 3) * HDIM + tid], a3);
            }
            hs[tid] = fmaxf((a0 + a1) + (a2 + a3), 0.0f);
        }
        __syncthreads();
        // Z main: 4096 chunks of 8 halves, 16 per thread
#pragma unroll
        for (int r = 0; r < 16; r++) {
            int chunk = r * 256 + tid;
            int k0 = chunk * 8;
            float h = hs[k0 >> 8];
            const float* xr = xs + (k0 & 255);
            union { __half e[8]; uint4 v; } o;
#pragma unroll
            for (int j = 0; j < 8; j++) o.e[j] = __float2half_rn(h * xr[j]);
            ((uint4*)g_Z)[(size_t)b * (KTOT / 8) + chunk] = o.v;
        }
        // Zext = [x | h]
        g_Zext[b * KE + tid] = __float2half_rn(xs[tid]);
        if (tid < HDIM) g_Zext[b * KE + 256 + tid] = __float2half_rn(hs[tid]);
    } else if (bid < ZB + WMB) {
        // ---- W main: g_W[k][o] = fp16(w2[(k>>8)*W2COLS + (k&255)*256 + o]) ----
        int u = (bid - ZB) * 256 + tid;       // uint4 chunk id (8 halves)
        int j0 = u * 8;                        // output half index = k*256 + o
        int k = j0 >> 8;
        size_t in = (size_t)(k >> 8) * W2COLS + (size_t)(k & 255) * 256 + (j0 & 255);
        float4 v0 = *(const float4*)(w2 + in);
        float4 v1 = *(const float4*)(w2 + in + 4);
        union { __half e[8]; uint4 v; } o;
        o.e[0] = __float2half_rn(v0.x); o.e[1] = __float2half_rn(v0.y);
        o.e[2] = __float2half_rn(v0.z); o.e[3] = __float2half_rn(v0.w);
        o.e[4] = __float2half_rn(v1.x); o.e[5] = __float2half_rn(v1.y);
        o.e[6] = __float2half_rn(v1.z); o.e[7] = __float2half_rn(v1.w);
        ((uint4*)g_W)[u] = o.v;
    } else {
        // ---- Wext: [k][o], k<256: baseW+b2; k>=256: w2 bias columns ----
        int u = (bid - ZB - WMB) * 256 + tid;
        int j0 = u * 8;
        int k = j0 >> 8, o0 = j0 & 255;
        float v[8];
        if (k < 256) {
            float4 a0 = *(const float4*)(baseW + k * ODIM + o0);
            float4 a1 = *(const float4*)(baseW + k * ODIM + o0 + 4);
            float4 c0 = *(const float4*)(b2 + k * ODIM + o0);
            float4 c1 = *(const float4*)(b2 + k * ODIM + o0 + 4);
            v[0]=a0.x+c0.x; v[1]=a0.y+c0.y; v[2]=a0.z+c0.z; v[3]=a0.w+c0.w;
            v[4]=a1.x+c1.x; v[5]=a1.y+c1.y; v[6]=a1.z+c1.z; v[7]=a1.w+c1.w;
        } else {
            const float* src = w2 + (size_t)(k - 256) * W2COLS + IO + o0;
            float4 a0 = *(const float4*)(src);
            float4 a1 = *(const float4*)(src + 4);
            v[0]=a0.x; v[1]=a0.y; v[2]=a0.z; v[3]=a0.w;
            v[4]=a1.x; v[5]=a1.y; v[6]=a1.z; v[7]=a1.w;
        }
        union { __half e[8]; uint4 v; } o;
#pragma unroll
        for (int j = 0; j < 8; j++) o.e[j] = __float2half_rn(v[j]);
        ((uint4*)g_Wext)[u] = o.v;
    }
}

// ------------------------- HMMA GEMM (mma.sync fp16, 1-term) ----------------
// C = Z@W (+ ext), W stored [k][o]. BM=256 x BN=128, 256 threads (8 warps,
// 4m x 2n, warp 64x64), BK=64, 4-stage cp.async pipeline (192 KB).
// grid 2x2x37 = 148 CTAs (one per SM). B consumed via ldmatrix.trans.
#define STG_BYTES 49152
#define OFF_A 0
#define OFF_B 32768
#define SMEM_TOTAL (4 * STG_BYTES)   // 192 KB

__global__ void __launch_bounds__(256, 1)
gemm_hmma_kernel() {
    extern __shared__ char smem[];
    const uint32_t sbase = smem_u32(smem);
    const int tid = threadIdx.x;
    const int wid = tid >> 5, lane = tid & 31;
    const int n0 = blockIdx.x * BN;
    const int m0 = blockIdx.y * BM;
    const int z = blockIdx.z;
    const bool mixed = (z == NSLICES - 1);

    const int m_base = (wid >> 1) * 64;   // 4 warps along M
    const int n_base = (wid & 1) * 64;    // 2 warps along N

    auto load_stage = [&](int kt) {
        uint32_t sb = sbase + (uint32_t)(kt & 3) * STG_BYTES;
        const __half* A;
        const __half* B;
        size_t kstrA;
        int kb;
        if (!mixed || kt < 8) {
            A = g_Z; B = g_W; kstrA = KTOT;
            kb = (z * NST + kt) * BK;
        } else {
            A = g_Zext; B = g_Wext; kstrA = KE;
            kb = (kt - 8) * BK;
        }
        // A: 256 rows x 128B -> 2048 chunks, 8 per thread
#pragma unroll
        for (int i = 0; i < 8; i++) {
            int t = tid + i * 256;
            int row = t >> 3, ch = t & 7;
            uint32_t sw = (uint32_t)row * 128 + ((ch ^ (row & 7)) << 4);
            cp16(sb + OFF_A + sw, A + (size_t)(m0 + row) * kstrA + kb + ch * 8);
        }
        // B: 64 k-rows x 256B -> 1024 chunks, 4 per thread ([k][o] layout)
#pragma unroll
        for (int i = 0; i < 4; i++) {
            int t = tid + i * 256;
            int row = t >> 4, ch = t & 15;
            uint32_t sw = (uint32_t)row * 256 + ((ch ^ (row & 7)) << 4);
            cp16(sb + OFF_B + sw, B + (size_t)(kb + row) * ODIM + n0 + ch * 8);
        }
    };

    float acc[4][8][4];
#pragma unroll
    for (int i = 0; i < 4; i++)
#pragma unroll
        for (int j = 0; j < 8; j++)
#pragma unroll
            for (int q = 0; q < 4; q++) acc[i][j][q] = 0.0f;

    const int arow_base = m_base + (lane & 15);
    const int asel = lane >> 4;
    const int brow_lane = lane & 15;          // k-row within k16 step
    const int bch_lane = (lane >> 4) & 1;     // n8 group select

    load_stage(0); CP_COMMIT();
    load_stage(1); CP_COMMIT();
    load_stage(2); CP_COMMIT();

    for (int kt = 0; kt < NST; kt++) {
        CP_WAIT(2);
        __syncthreads();
        if (kt + 3 < NST) load_stage(kt + 3);
        CP_COMMIT();

        uint32_t sb = sbase + (uint32_t)(kt & 3) * STG_BYTES;

#pragma unroll
        for (int kk = 0; kk < 4; kk++) {
            uint32_t a[4][4], bt[4][4];
#pragma unroll
            for (int mf = 0; mf < 4; mf++) {
                int row = arow_base + mf * 16;
                int ch = 2 * kk + asel;
                uint32_t ad = sb + OFF_A + row * 128 + ((ch ^ (row & 7)) << 4);
                LDSM4(a[mf][0], a[mf][1], a[mf][2], a[mf][3], ad);
            }
#pragma unroll
            for (int np = 0; np < 4; np++) {
                int row = kk * 16 + brow_lane;
                int ch = (n_base >> 3) + np * 2 + bch_lane;
                uint32_t bd = sb + OFF_B + row * 256 + ((ch ^ (row & 7)) << 4);
                LDSM4T(bt[np][0], bt[np][1], bt[np][2], bt[np][3], bd);
            }
#pragma unroll
            for (int mf = 0; mf < 4; mf++)
#pragma unroll
                for (int np = 0; np < 4; np++) {
                    MMA16816(acc[mf][2 * np], a[mf], bt[np][0], bt[np][1]);
                    MMA16816(acc[mf][2 * np + 1], a[mf], bt[np][2], bt[np][3]);
                }
        }
    }
    CP_WAIT(0);

    float* dst = g_part + (size_t)z * (BATCH * ODIM);
#pragma unroll
    for (int mf = 0; mf < 4; mf++) {
#pragma unroll
        for (int nf = 0; nf < 8; nf++) {
            int m = m0 + m_base + mf * 16 + (lane >> 2);
            int o = n0 + n_base + nf * 8 + (lane & 3) * 2;
            float2 v0 = make_float2(acc[mf][nf][0], acc[mf][nf][1]);
            float2 v1 = make_float2(acc[mf][nf][2], acc[mf][nf][3]);
            *(float2*)(dst + (size_t)m * ODIM + o) = v0;
            *(float2*)(dst + (size_t)(m + 8) * ODIM + o) = v1;
        }
    }
}

// ------------------------- split-K reduction + bias --------------------------
__global__ void reduce_kernel(const float* __restrict__ base_bias,
                              const float* __restrict__ b2,
                              float* __restrict__ out) {
    int b = blockIdx.x, o = threadIdx.x;
    float acc = base_bias[o] + b2[IO + o];
#pragma unroll
    for (int s = 0; s < NSLICES; s++)
        acc += g_part[((size_t)s * BATCH + b) * ODIM + o];
    out[b * ODIM + o] = acc;
}

// ------------------------- launcher -----------------------------------------
extern "C" void kernel_launch(void* const* d_in, const int* in_sizes, int n_in,
                              void* d_out, int out_size) {
    const float* x    = (const float*)d_in[0];
    const float* cond = (const float*)d_in[1];
    const float* bw   = (const float*)d_in[2];
    const float* bb   = (const float*)d_in[3];
    const float* w1   = (const float*)d_in[4];
    const float* b1   = (const float*)d_in[5];
    const float* w2   = (const float*)d_in[6];
    const float* b2   = (const float*)d_in[7];
    float* out = (float*)d_out;

    cudaFuncSetAttribute(gemm_hmma_kernel,
                         cudaFuncAttributeMaxDynamicSharedMemorySize, SMEM_TOTAL);

    prep_all_kernel<<<NBLK, 256>>>(x, cond, w1, b1, w2, bw, b2);
    gemm_hmma_kernel<<<dim3(ODIM / BN, BATCH / BM, NSLICES), 256, SMEM_TOTAL>>>();
    reduce_kernel<<<BATCH, 256>>>(bb, b2, out);
}

// round 12
// speedup vs baseline: 5.9675x; 1.2705x over previous
#include <cuda_runtime.h>
#include <cuda_fp16.h>
#include <cstdint>

#define BATCH 512
#define IDIM 256
#define ODIM 256
#define CDIM 128
#define HDIM 128
#define IO (IDIM * ODIM)        // 65536
#define W2COLS (IO + ODIM)      // 65792
#define KTOT (HDIM * IDIM)      // 32768
#define KE 384                  // extended K: 256 (x/base) + 128 (h/biascols)
#define NSLICES 37              // 36 x (14 main BK) + 1 x (8 main + 6 ext BK)
#define BM 256
#define BN 128
#define BK 64
#define NST 14                  // stages per slice (uniform)

// ------------------------- device scratch (no allocs) -----------------------
__device__ __half g_X[(size_t)BATCH * IDIM];                // 256 KB, [b][i]
__device__ __half g_H[(size_t)129 * BATCH];                 // [hh][b]; row 128 = 1.0
__device__ __half g_W[(size_t)KTOT * ODIM];                 // 16 MB, [k][o]
__device__ __half g_Zext[(size_t)BATCH * KE];
__device__ __half g_Wext[(size_t)KE * ODIM];                // [k][o]
__device__ float g_part[(size_t)NSLICES * BATCH * ODIM];

// ------------------------- PTX helpers --------------------------------------
__device__ __forceinline__ uint32_t smem_u32(const void* p) {
    uint32_t a;
    asm("{ .reg .u64 t; cvta.to.shared.u64 t, %1; cvt.u32.u64 %0, t; }"
        : "=r"(a) : "l"(p));
    return a;
}
__device__ __forceinline__ void cp16(uint32_t s, const void* g) {
    asm volatile("cp.async.cg.shared.global [%0], [%1], 16;" :: "r"(s), "l"(g));
}
#define CP_COMMIT() asm volatile("cp.async.commit_group;" ::: "memory")
#define CP_WAIT(n)  asm volatile("cp.async.wait_group %0;" :: "n"(n) : "memory")

#define LDSM4(r0, r1, r2, r3, addr) \
    asm volatile("ldmatrix.sync.aligned.m8n8.x4.shared.b16 {%0,%1,%2,%3}, [%4];" \
        : "=r"(r0), "=r"(r1), "=r"(r2), "=r"(r3) : "r"(addr))

#define LDSM4T(r0, r1, r2, r3, addr) \
    asm volatile("ldmatrix.sync.aligned.m8n8.x4.trans.shared.b16 {%0,%1,%2,%3}, [%4];" \
        : "=r"(r0), "=r"(r1), "=r"(r2), "=r"(r3) : "r"(addr))

#define MMA16816(c, a, b0, b1) \
    asm volatile("mma.sync.aligned.m16n8k16.row.col.f32.f16.f16.f32 " \
        "{%0,%1,%2,%3}, {%4,%5,%6,%7}, {%8,%9}, {%0,%1,%2,%3};" \
        : "+f"((c)[0]), "+f"((c)[1]), "+f"((c)[2]), "+f"((c)[3]) \
        : "r"((a)[0]), "r"((a)[1]), "r"((a)[2]), "r"((a)[3]), "r"(b0), "r"(b1))

#define HMUL2(d, s) asm volatile("mul.f16x2 %0, %0, %1;" : "+r"(d) : "r"(s))

// ------------------------- fused prep kernel ---------------------------------
// blocks [0, 512):       one block per batch row: h, g_X row, g_H col, Zext
// blocks [512, 4608):    W main (pure streaming fp32->fp16, [k][o] layout)
// blocks [4608, 4656):   Wext (streaming, [k][o])
#define ZB 512
#define WMB 4096                // KTOT*ODIM/8/256
#define WEB 48                  // KE*ODIM/8/256
#define NBLK (ZB + WMB + WEB)   // 4656

__global__ void __launch_bounds__(256)
prep_all_kernel(const float* __restrict__ x,
                const float* __restrict__ cond,
                const float* __restrict__ w1,
                const float* __restrict__ b1,
                const float* __restrict__ w2,
                const float* __restrict__ baseW,
                const float* __restrict__ b2) {
    __shared__ float cs[CDIM];
    __shared__ float xs[IDIM];
    const int bid = blockIdx.x;
    const int tid = threadIdx.x;

    if (bid < ZB) {
        // ---- one block per batch row b ----
        const int b = bid;
        if (tid < CDIM) cs[tid] = cond[b * CDIM + tid];
        xs[tid] = x[b * IDIM + tid];
        __syncthreads();
        // x row -> fp16 table + Zext[:256]
        __half xh = __float2half_rn(xs[tid]);
        g_X[b * IDIM + tid] = xh;
        g_Zext[b * KE + tid] = xh;
        if (tid < HDIM) {
            float a0 = b1[tid], a1 = 0.f, a2 = 0.f, a3 = 0.f;
#pragma unroll 8
            for (int k = 0; k < CDIM; k += 4) {
                a0 = fmaf(cs[k],     w1[(k)     * HDIM + tid], a0);
                a1 = fmaf(cs[k + 1], w1[(k + 1) * HDIM + tid], a1);
                a2 = fmaf(cs[k + 2], w1[(k + 2) * HDIM + tid], a2);
                a3 = fmaf(cs[k + 3], w1[(k + 3) * HDIM + tid], a3);
            }
            __half hv = __float2half_rn(fmaxf((a0 + a1) + (a2 + a3), 0.0f));
            g_H[tid * BATCH + b] = hv;          // [hh][b]
            g_Zext[b * KE + 256 + tid] = hv;
        }
        if (tid == 255) g_H[128 * BATCH + b] = __float2half_rn(1.0f);  // ones row
    } else if (bid < ZB + WMB) {
        // ---- W main: g_W[k][o] = fp16(w2[(k>>8)*W2COLS + (k&255)*256 + o]) ----
        int u = (bid - ZB) * 256 + tid;       // uint4 chunk id (8 halves)
        int j0 = u * 8;                        // output half index = k*256 + o
        int k = j0 >> 8;
        size_t in = (size_t)(k >> 8) * W2COLS + (size_t)(k & 255) * 256 + (j0 & 255);
        float4 v0 = *(const float4*)(w2 + in);
        float4 v1 = *(const float4*)(w2 + in + 4);
        union { __half e[8]; uint4 v; } o;
        o.e[0] = __float2half_rn(v0.x); o.e[1] = __float2half_rn(v0.y);
        o.e[2] = __float2half_rn(v0.z); o.e[3] = __float2half_rn(v0.w);
        o.e[4] = __float2half_rn(v1.x); o.e[5] = __float2half_rn(v1.y);
        o.e[6] = __float2half_rn(v1.z); o.e[7] = __float2half_rn(v1.w);
        ((uint4*)g_W)[u] = o.v;
    } else {
        // ---- Wext: [k][o], k<256: baseW+b2; k>=256: w2 bias columns ----
        int u = (bid - ZB - WMB) * 256 + tid;
        int j0 = u * 8;
        int k = j0 >> 8, o0 = j0 & 255;
        float v[8];
        if (k < 256) {
            float4 a0 = *(const float4*)(baseW + k * ODIM + o0);
            float4 a1 = *(const float4*)(baseW + k * ODIM + o0 + 4);
            float4 c0 = *(const float4*)(b2 + k * ODIM + o0);
            float4 c1 = *(const float4*)(b2 + k * ODIM + o0 + 4);
            v[0]=a0.x+c0.x; v[1]=a0.y+c0.y; v[2]=a0.z+c0.z; v[3]=a0.w+c0.w;
            v[4]=a1.x+c1.x; v[5]=a1.y+c1.y; v[6]=a1.z+c1.z; v[7]=a1.w+c1.w;
        } else {
            const float* src = w2 + (size_t)(k - 256) * W2COLS + IO + o0;
            float4 a0 = *(const float4*)(src);
            float4 a1 = *(const float4*)(src + 4);
            v[0]=a0.x; v[1]=a0.y; v[2]=a0.z; v[3]=a0.w;
            v[4]=a1.x; v[5]=a1.y; v[6]=a1.z; v[7]=a1.w;
        }
        union { __half e[8]; uint4 v; } o;
#pragma unroll
        for (int j = 0; j < 8; j++) o.e[j] = __float2half_rn(v[j]);
        ((uint4*)g_Wext)[u] = o.v;
    }
}

// ------------------------- HMMA GEMM (A generated on the fly) ---------------
// C = (h∘x)@W (+ ext). A-tile = x fp16 tile, scaled by h[row][hh] in registers
// after LDSM (hh is constant within a BK=64 stage). BM=256 x BN=128,
// 256 threads (8 warps, 4m x 2n, warp 64x64), BK=64, 4-stage pipeline.
// grid 2x2x37 = 148 CTAs. Ext stages use g_Zext with the ones-row hh=128.
#define STG_BYTES 49664          // A 32K + B 16K + h 512 + pad
#define OFF_A 0
#define OFF_B 32768
#define OFF_H 49152
#define SMEM_TOTAL (4 * STG_BYTES)   // 198656

__global__ void __launch_bounds__(256, 1)
gemm_hmma_kernel() {
    extern __shared__ char smem[];
    const uint32_t sbase = smem_u32(smem);
    const int tid = threadIdx.x;
    const int wid = tid >> 5, lane = tid & 31;
    const int n0 = blockIdx.x * BN;
    const int m0 = blockIdx.y * BM;
    const int z = blockIdx.z;
    const bool mixed = (z == NSLICES - 1);

    const int m_base = (wid >> 1) * 64;   // 4 warps along M
    const int n_base = (wid & 1) * 64;    // 2 warps along N

    auto load_stage = [&](int kt) {
        uint32_t sb = sbase + (uint32_t)(kt & 3) * STG_BYTES;
        const __half* A;
        const __half* B;
        size_t kstrA;
        int kb, hh;
        if (!mixed || kt < 8) {
            int k0 = (z * NST + kt) * BK;
            hh = k0 >> 8;
            A = g_X; kstrA = IDIM; kb = k0 & 255;
            B = g_W + (size_t)k0 * ODIM;
        } else {
            A = g_Zext; kstrA = KE; kb = (kt - 8) * BK;
            hh = 128;
            B = g_Wext + (size_t)kb * ODIM;
        }
        // A: 256 rows x 128B -> 2048 chunks, 8 per thread
#pragma unroll
        for (int i = 0; i < 8; i++) {
            int t = tid + i * 256;
            int row = t >> 3, ch = t & 7;
            uint32_t sw = (uint32_t)row * 128 + ((ch ^ (row & 7)) << 4);
            cp16(sb + OFF_A + sw, A + (size_t)(m0 + row) * kstrA + kb + ch * 8);
        }
        // B: 64 k-rows x 256B -> 1024 chunks, 4 per thread ([k][o] layout)
#pragma unroll
        for (int i = 0; i < 4; i++) {
            int t = tid + i * 256;
            int row = t >> 4, ch = t & 15;
            uint32_t sw = (uint32_t)row * 256 + ((ch ^ (row & 7)) << 4);
            cp16(sb + OFF_B + sw, B + (size_t)row * ODIM + n0 + ch * 8);
        }
        // h column for this stage's hh: 256 rows x 2B = 512B = 32 chunks
        if (tid < 32)
            cp16(sb + OFF_H + tid * 16, g_H + hh * BATCH + m0 + tid * 8);
    };

    float acc[4][8][4];
#pragma unroll
    for (int i = 0; i < 4; i++)
#pragma unroll
        for (int j = 0; j < 8; j++)
#pragma unroll
            for (int q = 0; q < 4; q++) acc[i][j][q] = 0.0f;

    const int arow_base = m_base + (lane & 15);
    const int asel = lane >> 4;
    const int brow_lane = lane & 15;          // k-row within k16 step
    const int bch_lane = (lane >> 4) & 1;     // n8 group select
    const int hrow = m_base + (lane >> 2);    // fragment-owner row

    load_stage(0); CP_COMMIT();
    load_stage(1); CP_COMMIT();
    load_stage(2); CP_COMMIT();

    for (int kt = 0; kt < NST; kt++) {
        CP_WAIT(2);
        __syncthreads();
        if (kt + 3 < NST) load_stage(kt + 3);
        CP_COMMIT();

        uint32_t sb = sbase + (uint32_t)(kt & 3) * STG_BYTES;

        // per-stage h scalars (packed to half2) for the 4 m-fragments
        uint32_t hq[4][2];
        uint32_t hbase = sb + OFF_H + (uint32_t)hrow * 2;
#pragma unroll
        for (int mf = 0; mf < 4; mf++) {
            uint32_t t0, t1;
            asm volatile("ld.shared.u16 %0, [%1];" : "=r"(t0) : "r"(hbase + mf * 32));
            asm volatile("ld.shared.u16 %0, [%1];" : "=r"(t1) : "r"(hbase + mf * 32 + 16));
            hq[mf][0] = t0 | (t0 << 16);
            hq[mf][1] = t1 | (t1 << 16);
        }

#pragma unroll
        for (int kk = 0; kk < 4; kk++) {
            uint32_t a[4][4], bt[4][4];
#pragma unroll
            for (int mf = 0; mf < 4; mf++) {
                int row = arow_base + mf * 16;
                int ch = 2 * kk + asel;
                uint32_t ad = sb + OFF_A + row * 128 + ((ch ^ (row & 7)) << 4);
                LDSM4(a[mf][0], a[mf][1], a[mf][2], a[mf][3], ad);
                // scale by h: regs {0,2} own row hrow+mf*16, {1,3} own +8
                HMUL2(a[mf][0], hq[mf][0]);
                HMUL2(a[mf][2], hq[mf][0]);
                HMUL2(a[mf][1], hq[mf][1]);
                HMUL2(a[mf][3], hq[mf][1]);
            }
#pragma unroll
            for (int np = 0; np < 4; np++) {
                int row = kk * 16 + brow_lane;
                int ch = (n_base >> 3) + np * 2 + bch_lane;
                uint32_t bd = sb + OFF_B + row * 256 + ((ch ^ (row & 7)) << 4);
                LDSM4T(bt[np][0], bt[np][1], bt[np][2], bt[np][3], bd);
            }
#pragma unroll
            for (int mf = 0; mf < 4; mf++)
#pragma unroll
                for (int np = 0; np < 4; np++) {
                    MMA16816(acc[mf][2 * np], a[mf], bt[np][0], bt[np][1]);
                    MMA16816(acc[mf][2 * np + 1], a[mf], bt[np][2], bt[np][3]);
                }
        }
    }
    CP_WAIT(0);

    float* dst = g_part + (size_t)z * (BATCH * ODIM);
#pragma unroll
    for (int mf = 0; mf < 4; mf++) {
#pragma unroll
        for (int nf = 0; nf < 8; nf++) {
            int m = m0 + m_base + mf * 16 + (lane >> 2);
            int o = n0 + n_base + nf * 8 + (lane & 3) * 2;
            float2 v0 = make_float2(acc[mf][nf][0], acc[mf][nf][1]);
            float2 v1 = make_float2(acc[mf][nf][2], acc[mf][nf][3]);
            *(float2*)(dst + (size_t)m * ODIM + o) = v0;
            *(float2*)(dst + (size_t)(m + 8) * ODIM + o) = v1;
        }
    }
}

// ------------------------- split-K reduction + bias --------------------------
__global__ void reduce_kernel(const float* __restrict__ base_bias,
                              const float* __restrict__ b2,
                              float* __restrict__ out) {
    int b = blockIdx.x, o = threadIdx.x;
    float acc = base_bias[o] + b2[IO + o];
#pragma unroll
    for (int s = 0; s < NSLICES; s++)
        acc += g_part[((size_t)s * BATCH + b) * ODIM + o];
    out[b * ODIM + o] = acc;
}

// ------------------------- launcher -----------------------------------------
extern "C" void kernel_launch(void* const* d_in, const int* in_sizes, int n_in,
                              void* d_out, int out_size) {
    const float* x    = (const float*)d_in[0];
    const float* cond = (const float*)d_in[1];
    const float* bw   = (const float*)d_in[2];
    const float* bb   = (const float*)d_in[3];
    const float* w1   = (const float*)d_in[4];
    const float* b1   = (const float*)d_in[5];
    const float* w2   = (const float*)d_in[6];
    const float* b2   = (const float*)d_in[7];
    float* out = (float*)d_out;

    cudaFuncSetAttribute(gemm_hmma_kernel,
                         cudaFuncAttributeMaxDynamicSharedMemorySize, SMEM_TOTAL);

    prep_all_kernel<<<NBLK, 256>>>(x, cond, w1, b1, w2, bw, b2);
    gemm_hmma_kernel<<<dim3(ODIM / BN, BATCH / BM, NSLICES), 256, SMEM_TOTAL>>>();
    reduce_kernel<<<BATCH, 256>>>(bb, b2, out);
}